// round 1
// baseline (speedup 1.0000x reference)
#include <cuda_runtime.h>
#include <math.h>

#define E_DIM   768
#define S_DIM   1024
#define B_DIM   4
#define H_DIM   12
#define V_DIM   50257
#define DFF_DIM 3072
#define Q_DIM   1025   // S+1

// ------------------------- scratch (static device globals) -------------------------
__device__ float g_meanWe[E_DIM];
__device__ float g_v    [(long)B_DIM*S_DIM*E_DIM];
__device__ float g_bvec [B_DIM*E_DIM];
__device__ float g_Q    [(long)H_DIM*Q_DIM*E_DIM];
__device__ float g_K    [(long)H_DIM*S_DIM*E_DIM];
__device__ float g_attnT[(long)Q_DIM*H_DIM*S_DIM];           // (q, h*S+s)
__device__ float g_Vt   [(long)B_DIM*H_DIM*S_DIM*E_DIM];     // (b, h*S+s, e)
__device__ float g_f    [(long)B_DIM*Q_DIM*E_DIM];
__device__ float g_h1   [(long)B_DIM*Q_DIM*DFF_DIM];
__device__ float g_f2   [(long)B_DIM*Q_DIM*E_DIM];

// ------------------------- small kernels -------------------------
__global__ void zero_mean_k() {
    if (threadIdx.x < E_DIM) g_meanWe[threadIdx.x] = 0.0f;
}

// column mean of W_e (V x E): E_W_e row (all rows identical since T = ones)
__global__ void colmean_k(const float* __restrict__ W_e) {
    int e = blockIdx.x * 256 + threadIdx.x;       // gridDim.x = 3 -> 768 cols
    int chunk = blockIdx.y;                       // gridDim.y = 64
    const int CH = (V_DIM + 63) / 64;             // 786
    int v0 = chunk * CH;
    int v1 = v0 + CH; if (v1 > V_DIM) v1 = V_DIM;
    float s = 0.0f;
    for (int v = v0; v < v1; v++) s += W_e[(long)v * E_DIM + e];
    atomicAdd(&g_meanWe[e], s * (1.0f / 50257.0f));
}

// v[b,s,e] = W_e[x[b,s], e] - mean[e]
__global__ void embed_k(const int* __restrict__ x, const float* __restrict__ W_e) {
    long i = (long)blockIdx.x * blockDim.x + threadIdx.x;
    const long n = (long)B_DIM * S_DIM * E_DIM;
    if (i >= n) return;
    int e = (int)(i % E_DIM);
    long bs = i / E_DIM;
    g_v[i] = W_e[(long)x[bs] * E_DIM + e] - g_meanWe[e];
}

// bvec[b,e] = B_lr * sum_s v[b,s,e] / S   (this is delta_B / s, used as a bias)
__global__ void bvec_k(const float* __restrict__ Blr) {
    int b = blockIdx.x;
    int e = threadIdx.x;   // 768 threads
    const float* vb = g_v + (long)b * S_DIM * E_DIM + e;
    float s = 0.0f;
    for (int t = 0; t < S_DIM; t++) s += vb[(long)t * E_DIM];
    g_bvec[b * E_DIM + e] = s * Blr[0] * (1.0f / (float)S_DIM);
}

// softmax over each 1024-chunk:  attnT[q, h*1024 .. h*1024+1023], scaled by 1/sqrt(768)
__global__ void softmax_k(float* __restrict__ attnT) {
    int q = blockIdx.x / H_DIM;
    int h = blockIdx.x % H_DIM;
    float* row = attnT + (long)q * (H_DIM * S_DIM) + (long)h * S_DIM;
    int tid = threadIdx.x;   // 256 threads x 4 elems
    const float scale = 0.03608439182435161f;   // 1/sqrt(768)
    float4 v = reinterpret_cast<float4*>(row)[tid];
    float m = fmaxf(fmaxf(v.x, v.y), fmaxf(v.z, v.w));
    __shared__ float red[8];
    #pragma unroll
    for (int o = 16; o > 0; o >>= 1) m = fmaxf(m, __shfl_xor_sync(0xffffffffu, m, o));
    if ((tid & 31) == 0) red[tid >> 5] = m;
    __syncthreads();
    m = red[0];
    #pragma unroll
    for (int w = 1; w < 8; w++) m = fmaxf(m, red[w]);
    float ex = expf(scale * (v.x - m));
    float ey = expf(scale * (v.y - m));
    float ez = expf(scale * (v.z - m));
    float ew = expf(scale * (v.w - m));
    float s = ex + ey + ez + ew;
    #pragma unroll
    for (int o = 16; o > 0; o >>= 1) s += __shfl_xor_sync(0xffffffffu, s, o);
    __syncthreads();   // all reads of red (maxes) done
    if ((tid & 31) == 0) red[tid >> 5] = s;
    __syncthreads();
    s = 0.0f;
    #pragma unroll
    for (int w = 0; w < 8; w++) s += red[w];
    float inv = 1.0f / s;
    v.x = ex * inv; v.y = ey * inv; v.z = ez * inv; v.w = ew * inv;
    reinterpret_cast<float4*>(row)[tid] = v;
}

// ------------------------- generic SGEMM -------------------------
// C[m,n] = alpha * sum_k A[m,k] * B(k,n) (+ bias[n])  [+ exact GELU]
// BT=true : B is (N x K) row-major (we use B[n,k])  -> "NT"
// BT=false: B is (K x N) row-major (we use B[k,n])  -> "NN"
// batching via blockIdx.z:
//   A += (z / divA) * sA;  B += (z % modB) * sB;  C += z * sC
//   alpha = alphaScale * (alphaPtr ? alphaPtr[z % alphaMod] : 1)
//   bias  = biasPtr ? biasPtr + z * biasStride : null
template<bool BT, bool GELU>
__global__ __launch_bounds__(256, 2)
void gemm_k(const float* __restrict__ Ag, const float* __restrict__ Bg,
            float* __restrict__ Cg,
            int M, int N, int K, int lda, int ldb, int ldc,
            long sA, long sB, long sC, int divA, int modB,
            const float* __restrict__ alphaPtr, int alphaMod, float alphaScale,
            const float* __restrict__ biasPtr, long biasStride)
{
    int z = blockIdx.z;
    const float* A = Ag + (long)(z / divA) * sA;
    const float* B = Bg + (long)(z % modB) * sB;
    float* C = Cg + (long)z * sC;
    float alpha = alphaScale;
    if (alphaPtr) alpha *= alphaPtr[z % alphaMod];
    const float* bias = biasPtr ? (biasPtr + (long)z * biasStride) : nullptr;

    __shared__ float As[8][128];
    __shared__ float Bs[8][128];

    int bm = blockIdx.y * 128;
    int bn = blockIdx.x * 128;
    int tid = threadIdx.x;

    int arow = tid >> 1;           // 0..127
    int acol = (tid & 1) << 2;     // 0 or 4
    int ty = tid >> 4, tx = tid & 15;
    int trow = ty * 8, tcol = tx * 8;

    float acc[8][8];
    #pragma unroll
    for (int i = 0; i < 8; i++)
        #pragma unroll
        for (int j = 0; j < 8; j++) acc[i][j] = 0.0f;

    for (int k0 = 0; k0 < K; k0 += 8) {
        // A tile (BM x BK), store transposed
        float4 av = make_float4(0.f, 0.f, 0.f, 0.f);
        if (bm + arow < M)
            av = *reinterpret_cast<const float4*>(A + (long)(bm + arow) * lda + k0 + acol);
        As[acol + 0][arow] = av.x; As[acol + 1][arow] = av.y;
        As[acol + 2][arow] = av.z; As[acol + 3][arow] = av.w;

        if (BT) {
            float4 bv = make_float4(0.f, 0.f, 0.f, 0.f);
            if (bn + arow < N)
                bv = *reinterpret_cast<const float4*>(B + (long)(bn + arow) * ldb + k0 + acol);
            Bs[acol + 0][arow] = bv.x; Bs[acol + 1][arow] = bv.y;
            Bs[acol + 2][arow] = bv.z; Bs[acol + 3][arow] = bv.w;
        } else {
            int kr = tid >> 5;            // 0..7
            int nc = (tid & 31) << 2;     // 0..124
            int n = bn + nc;
            const float* src = B + (long)(k0 + kr) * ldb + n;
            float4 bv;
            if (n + 3 < N) {
                bv = *reinterpret_cast<const float4*>(src);
            } else {
                bv.x = (n + 0 < N) ? src[0] : 0.f;
                bv.y = (n + 1 < N) ? src[1] : 0.f;
                bv.z = (n + 2 < N) ? src[2] : 0.f;
                bv.w = (n + 3 < N) ? src[3] : 0.f;
            }
            *reinterpret_cast<float4*>(&Bs[kr][nc]) = bv;
        }
        __syncthreads();

        #pragma unroll
        for (int kk = 0; kk < 8; kk++) {
            float4 a0 = *reinterpret_cast<const float4*>(&As[kk][trow]);
            float4 a1 = *reinterpret_cast<const float4*>(&As[kk][trow + 4]);
            float4 b0 = *reinterpret_cast<const float4*>(&Bs[kk][tcol]);
            float4 b1 = *reinterpret_cast<const float4*>(&Bs[kk][tcol + 4]);
            float ar[8] = {a0.x, a0.y, a0.z, a0.w, a1.x, a1.y, a1.z, a1.w};
            float br[8] = {b0.x, b0.y, b0.z, b0.w, b1.x, b1.y, b1.z, b1.w};
            #pragma unroll
            for (int i = 0; i < 8; i++)
                #pragma unroll
                for (int j = 0; j < 8; j++)
                    acc[i][j] += ar[i] * br[j];
        }
        __syncthreads();
    }

    #pragma unroll
    for (int i = 0; i < 8; i++) {
        int m = bm + trow + i;
        if (m >= M) continue;
        float* crow = C + (long)m * ldc;
        #pragma unroll
        for (int j = 0; j < 8; j++) {
            int n = bn + tcol + j;
            if (n >= N) continue;
            float val = acc[i][j] * alpha;
            if (bias) val += bias[n];
            if (GELU) val = 0.5f * val * (1.0f + erff(val * 0.70710678118654752f));
            crow[n] = val;
        }
    }
}

// ------------------------- launch -------------------------
extern "C" void kernel_launch(void* const* d_in, const int* in_sizes, int n_in,
                              void* d_out, int out_size) {
    (void)in_sizes; (void)n_in; (void)out_size;
    const int*   x     = (const int*)  d_in[0];
    const float* W_e   = (const float*)d_in[1];
    const float* W_p   = (const float*)d_in[2];
    const float* W_q   = (const float*)d_in[3];
    const float* W_k   = (const float*)d_in[4];
    const float* W_v   = (const float*)d_in[5];
    const float* A_lr  = (const float*)d_in[6];
    const float* B_lr  = (const float*)d_in[7];
    const float* ff_w1 = (const float*)d_in[8];
    const float* ff_w2 = (const float*)d_in[9];
    float* out = (float*)d_out;

    float *p_v, *p_bvec, *p_Q, *p_K, *p_attnT, *p_Vt, *p_f, *p_h1, *p_f2;
    cudaGetSymbolAddress((void**)&p_v,     g_v);
    cudaGetSymbolAddress((void**)&p_bvec,  g_bvec);
    cudaGetSymbolAddress((void**)&p_Q,     g_Q);
    cudaGetSymbolAddress((void**)&p_K,     g_K);
    cudaGetSymbolAddress((void**)&p_attnT, g_attnT);
    cudaGetSymbolAddress((void**)&p_Vt,    g_Vt);
    cudaGetSymbolAddress((void**)&p_f,     g_f);
    cudaGetSymbolAddress((void**)&p_h1,    g_h1);
    cudaGetSymbolAddress((void**)&p_f2,    g_f2);

    const int BIG = 1 << 30;

    // mean of W_e columns
    zero_mean_k<<<1, 768>>>();
    {
        dim3 g(3, 64);
        colmean_k<<<g, 256>>>(W_e);
    }
    // v = W_e[x] - mean
    {
        long nv = (long)B_DIM * S_DIM * E_DIM;
        embed_k<<<(int)((nv + 255) / 256), 256>>>(x, W_e);
    }
    // bias vector (delta_B / s)
    bvec_k<<<B_DIM, E_DIM>>>(B_lr);

    // Q[h] = p(1025 x 768) @ W_q[h](768 x 768)     (NN)
    {
        dim3 g((E_DIM + 127) / 128, (Q_DIM + 127) / 128, H_DIM);
        gemm_k<false, false><<<g, 256>>>(W_p, W_q, p_Q,
            Q_DIM, E_DIM, E_DIM, E_DIM, E_DIM, E_DIM,
            0L, (long)E_DIM * E_DIM, (long)Q_DIM * E_DIM, 1, BIG,
            nullptr, 1, 1.0f, nullptr, 0L);
    }
    // K[h] = p[:-1](1024 x 768) @ W_k[h]           (NN)
    {
        dim3 g((E_DIM + 127) / 128, (S_DIM + 127) / 128, H_DIM);
        gemm_k<false, false><<<g, 256>>>(W_p, W_k, p_K,
            S_DIM, E_DIM, E_DIM, E_DIM, E_DIM, E_DIM,
            0L, (long)E_DIM * E_DIM, (long)S_DIM * E_DIM, 1, BIG,
            nullptr, 1, 1.0f, nullptr, 0L);
    }
    // attnT[q, h*1024+s] = Q[h,q,:] . K[h,s,:]     (NT), softmax handles 1/sqrt(d)
    {
        dim3 g((S_DIM + 127) / 128, (Q_DIM + 127) / 128, H_DIM);
        gemm_k<true, false><<<g, 256>>>(p_Q, p_K, p_attnT,
            Q_DIM, S_DIM, E_DIM, E_DIM, E_DIM, H_DIM * S_DIM,
            (long)Q_DIM * E_DIM, (long)S_DIM * E_DIM, (long)S_DIM, 1, BIG,
            nullptr, 1, 1.0f, nullptr, 0L);
    }
    softmax_k<<<Q_DIM * H_DIM, 256>>>(p_attnT);

    // Vt[b,h] = A_lr[h] * v[b](1024 x 768) @ W_v[h](768 x 768)   (NN), z = b*H + h
    {
        dim3 g((E_DIM + 127) / 128, (S_DIM + 127) / 128, B_DIM * H_DIM);
        gemm_k<false, false><<<g, 256>>>(p_v, W_v, p_Vt,
            S_DIM, E_DIM, E_DIM, E_DIM, E_DIM, E_DIM,
            (long)S_DIM * E_DIM, (long)E_DIM * E_DIM, (long)S_DIM * E_DIM, H_DIM, H_DIM,
            A_lr, H_DIM, 1.0f, nullptr, 0L);
    }
    // f[b] = (attnT(1025 x 12288) @ Vt[b](12288 x 768)) / S + bvec[b]   (NN)
    {
        dim3 g((E_DIM + 127) / 128, (Q_DIM + 127) / 128, B_DIM);
        gemm_k<false, false><<<g, 256>>>(p_attnT, p_Vt, p_f,
            Q_DIM, E_DIM, H_DIM * S_DIM, H_DIM * S_DIM, E_DIM, E_DIM,
            0L, (long)H_DIM * S_DIM * E_DIM, (long)Q_DIM * E_DIM, 1, BIG,
            nullptr, 1, 1.0f / (float)S_DIM, p_bvec, (long)E_DIM);
    }
    // h1 = gelu(f(4100 x 768) @ ff_w1^T(768 x 3072))    (NT + GELU)
    {
        dim3 g(DFF_DIM / 128, (B_DIM * Q_DIM + 127) / 128, 1);
        gemm_k<true, true><<<g, 256>>>(p_f, ff_w1, p_h1,
            B_DIM * Q_DIM, DFF_DIM, E_DIM, E_DIM, E_DIM, DFF_DIM,
            0L, 0L, 0L, 1, 1,
            nullptr, 1, 1.0f, nullptr, 0L);
    }
    // f2 = h1(4100 x 3072) @ ff_w2^T(3072 x 768)        (NT)
    {
        dim3 g(E_DIM / 128, (B_DIM * Q_DIM + 127) / 128, 1);
        gemm_k<true, false><<<g, 256>>>(p_h1, ff_w2, p_f2,
            B_DIM * Q_DIM, E_DIM, DFF_DIM, DFF_DIM, DFF_DIM, E_DIM,
            0L, 0L, 0L, 1, 1,
            nullptr, 1, 1.0f, nullptr, 0L);
    }
    // logits[b] = f2[b, :1024, :](1024 x 768) @ W_e^T(768 x 50257)   (NT), z = b
    {
        dim3 g((V_DIM + 127) / 128, (S_DIM + 127) / 128, B_DIM);
        gemm_k<true, false><<<g, 256>>>(p_f2, W_e, out,
            S_DIM, V_DIM, E_DIM, E_DIM, E_DIM, V_DIM,
            (long)Q_DIM * E_DIM, 0L, (long)S_DIM * V_DIM, 1, 1,
            nullptr, 1, 1.0f, nullptr, 0L);
    }
}

// round 3
// speedup vs baseline: 1.6505x; 1.6505x over previous
#include <cuda_runtime.h>
#include <math.h>
#include <stdint.h>

#define E_DIM   768
#define S_DIM   1024
#define B_DIM   4
#define H_DIM   12
#define V_DIM   50257
#define DFF_DIM 3072
#define Q_DIM   1025   // S+1

// ------------------------- scratch (static device globals) -------------------------
__device__ float g_meanWe[E_DIM];
__device__ float g_v    [(long)B_DIM*S_DIM*E_DIM];
__device__ float g_bvec [B_DIM*E_DIM];
__device__ float g_Q    [(long)H_DIM*Q_DIM*E_DIM];
__device__ float g_K    [(long)H_DIM*S_DIM*E_DIM];
__device__ float g_attnT[(long)Q_DIM*H_DIM*S_DIM];           // (q, h*S+s)
__device__ float g_Vt   [(long)B_DIM*H_DIM*S_DIM*E_DIM];     // (b, h*S+s, e)
__device__ float g_f    [(long)B_DIM*Q_DIM*E_DIM];
__device__ float g_h1   [(long)B_DIM*Q_DIM*DFF_DIM];
__device__ float g_f2   [(long)B_DIM*Q_DIM*E_DIM];

// ------------------------- small kernels -------------------------
__global__ void zero_mean_k() {
    if (threadIdx.x < E_DIM) g_meanWe[threadIdx.x] = 0.0f;
}

__global__ void colmean_k(const float* __restrict__ W_e) {
    int e = blockIdx.x * 256 + threadIdx.x;
    int chunk = blockIdx.y;
    const int CH = (V_DIM + 63) / 64;
    int v0 = chunk * CH;
    int v1 = v0 + CH; if (v1 > V_DIM) v1 = V_DIM;
    float s = 0.0f;
    for (int v = v0; v < v1; v++) s += W_e[(long)v * E_DIM + e];
    atomicAdd(&g_meanWe[e], s * (1.0f / 50257.0f));
}

__global__ void embed_k(const int* __restrict__ x, const float* __restrict__ W_e) {
    long i = (long)blockIdx.x * blockDim.x + threadIdx.x;
    const long n = (long)B_DIM * S_DIM * E_DIM;
    if (i >= n) return;
    int e = (int)(i % E_DIM);
    long bs = i / E_DIM;
    g_v[i] = W_e[(long)x[bs] * E_DIM + e] - g_meanWe[e];
}

__global__ void bvec_k(const float* __restrict__ Blr) {
    int b = blockIdx.x;
    int e = threadIdx.x;
    const float* vb = g_v + (long)b * S_DIM * E_DIM + e;
    float s = 0.0f;
    for (int t = 0; t < S_DIM; t++) s += vb[(long)t * E_DIM];
    g_bvec[b * E_DIM + e] = s * Blr[0] * (1.0f / (float)S_DIM);
}

__global__ void softmax_k(float* __restrict__ attnT) {
    int q = blockIdx.x / H_DIM;
    int h = blockIdx.x % H_DIM;
    float* row = attnT + (long)q * (H_DIM * S_DIM) + (long)h * S_DIM;
    int tid = threadIdx.x;
    const float scale = 0.03608439182435161f;   // 1/sqrt(768)
    float4 v = reinterpret_cast<float4*>(row)[tid];
    float m = fmaxf(fmaxf(v.x, v.y), fmaxf(v.z, v.w));
    __shared__ float red[8];
    #pragma unroll
    for (int o = 16; o > 0; o >>= 1) m = fmaxf(m, __shfl_xor_sync(0xffffffffu, m, o));
    if ((tid & 31) == 0) red[tid >> 5] = m;
    __syncthreads();
    m = red[0];
    #pragma unroll
    for (int w = 1; w < 8; w++) m = fmaxf(m, red[w]);
    float ex = expf(scale * (v.x - m));
    float ey = expf(scale * (v.y - m));
    float ez = expf(scale * (v.z - m));
    float ew = expf(scale * (v.w - m));
    float s = ex + ey + ez + ew;
    #pragma unroll
    for (int o = 16; o > 0; o >>= 1) s += __shfl_xor_sync(0xffffffffu, s, o);
    __syncthreads();
    if ((tid & 31) == 0) red[tid >> 5] = s;
    __syncthreads();
    s = 0.0f;
    #pragma unroll
    for (int w = 0; w < 8; w++) s += red[w];
    float inv = 1.0f / s;
    v.x = ex * inv; v.y = ey * inv; v.z = ez * inv; v.w = ew * inv;
    reinterpret_cast<float4*>(row)[tid] = v;
}

// ------------------------- tf32 tensor-core GEMM -------------------------
// C[m,n] = alpha * sum_k A[m,k] * B(k,n) (+ bias[n]) [+ exact GELU]
// BT=true : B is (N x K) row-major;  BT=false: B is (K x N) row-major.
// Block tile 128x128x32, 8 warps (2x4), warp tile 64x32, mma.m16n8k8.tf32.

#define LDT 40   // padded leading dim (floats)

__device__ __forceinline__ uint32_t f2tf(float f) {
    uint32_t u; asm("cvt.rna.tf32.f32 %0, %1;" : "=r"(u) : "f"(f)); return u;
}

__device__ __forceinline__ void mma8(float* c, const uint32_t* a, const uint32_t* b) {
    asm volatile("mma.sync.aligned.m16n8k8.row.col.f32.tf32.tf32.f32 "
        "{%0,%1,%2,%3}, {%4,%5,%6,%7}, {%8,%9}, {%0,%1,%2,%3};"
        : "+f"(c[0]), "+f"(c[1]), "+f"(c[2]), "+f"(c[3])
        : "r"(a[0]), "r"(a[1]), "r"(a[2]), "r"(a[3]), "r"(b[0]), "r"(b[1]));
}

template<bool BT, bool GELU>
__global__ __launch_bounds__(256, 2)
void gemm_tc(const float* __restrict__ Ag, const float* __restrict__ Bg,
             float* __restrict__ Cg,
             int M, int N, int K, int lda, int ldb, int ldc,
             long sA, long sB, long sC, int divA, int modB,
             const float* __restrict__ alphaPtr, int alphaMod, float alphaScale,
             const float* __restrict__ biasPtr, long biasStride)
{
    __shared__ float As[128 * LDT];
    __shared__ float Bs[128 * LDT];

    int z = blockIdx.z;
    const float* A = Ag + (long)(z / divA) * sA;
    const float* B = Bg + (long)(z % modB) * sB;
    float* C = Cg + (long)z * sC;
    float alpha = alphaScale;
    if (alphaPtr) alpha *= alphaPtr[z % alphaMod];
    const float* bias = biasPtr ? (biasPtr + (long)z * biasStride) : nullptr;

    int bm = blockIdx.y * 128;
    int bn = blockIdx.x * 128;
    int tid = threadIdx.x;
    int warp = tid >> 5, lane = tid & 31;
    int wm = warp >> 2, wn = warp & 3;      // 2 x 4 warp grid
    int g = lane >> 2, t = lane & 3;

    float acc[4][4][4];
    #pragma unroll
    for (int i = 0; i < 4; i++)
        #pragma unroll
        for (int j = 0; j < 4; j++)
            #pragma unroll
            for (int r = 0; r < 4; r++) acc[i][j][r] = 0.0f;

    int arow = tid >> 1;
    int acolg = (tid & 1) << 4;
    int bkr = tid >> 3;
    int bnc = (tid & 7) << 4;

    for (int k0 = 0; k0 < K; k0 += 32) {
        // ---- A tile ----
        {
            bool ok = (bm + arow) < M;
            const float* src = A + (long)(bm + arow) * lda + k0 + acolg;
            float* dst = As + arow * LDT;
            #pragma unroll
            for (int q = 0; q < 4; q++) {
                float4 v = ok ? *reinterpret_cast<const float4*>(src + q * 4)
                              : make_float4(0.f, 0.f, 0.f, 0.f);
                int kb = acolg + q * 4;
                int base8 = kb & 24;
                int off = (kb & 4) ? 1 : 0;
                dst[base8 + off + 0] = __uint_as_float(f2tf(v.x));
                dst[base8 + off + 2] = __uint_as_float(f2tf(v.y));
                dst[base8 + off + 4] = __uint_as_float(f2tf(v.z));
                dst[base8 + off + 6] = __uint_as_float(f2tf(v.w));
            }
        }
        // ---- B tile ----
        if (BT) {
            bool ok = (bn + arow) < N;
            const float* src = B + (long)(bn + arow) * ldb + k0 + acolg;
            float* dst = Bs + arow * LDT;
            #pragma unroll
            for (int q = 0; q < 4; q++) {
                float4 v = ok ? *reinterpret_cast<const float4*>(src + q * 4)
                              : make_float4(0.f, 0.f, 0.f, 0.f);
                int kb = acolg + q * 4;
                int base8 = kb & 24;
                int off = (kb & 4) ? 1 : 0;
                dst[base8 + off + 0] = __uint_as_float(f2tf(v.x));
                dst[base8 + off + 2] = __uint_as_float(f2tf(v.y));
                dst[base8 + off + 4] = __uint_as_float(f2tf(v.z));
                dst[base8 + off + 6] = __uint_as_float(f2tf(v.w));
            }
        } else {
            int base8 = bkr & 24;
            int kcol = base8 + (((bkr & 3) << 1) | ((bkr & 7) >> 2));
            const float* src = B + (long)(k0 + bkr) * ldb + bn + bnc;
            #pragma unroll
            for (int q = 0; q < 4; q++) {
                int n = bn + bnc + q * 4;
                float4 v;
                if (n + 3 < N) {
                    v = *reinterpret_cast<const float4*>(src + q * 4);
                } else {
                    v.x = (n + 0 < N) ? src[q * 4 + 0] : 0.f;
                    v.y = (n + 1 < N) ? src[q * 4 + 1] : 0.f;
                    v.z = (n + 2 < N) ? src[q * 4 + 2] : 0.f;
                    v.w = (n + 3 < N) ? src[q * 4 + 3] : 0.f;
                }
                int nl = bnc + q * 4;
                Bs[(nl + 0) * LDT + kcol] = __uint_as_float(f2tf(v.x));
                Bs[(nl + 1) * LDT + kcol] = __uint_as_float(f2tf(v.y));
                Bs[(nl + 2) * LDT + kcol] = __uint_as_float(f2tf(v.z));
                Bs[(nl + 3) * LDT + kcol] = __uint_as_float(f2tf(v.w));
            }
        }
        __syncthreads();

        #pragma unroll
        for (int ks = 0; ks < 4; ks++) {
            int kk = ks * 8;
            uint32_t af[4][4];
            #pragma unroll
            for (int i = 0; i < 4; i++) {
                int row = wm * 64 + i * 16 + g;
                float2 lo = *reinterpret_cast<const float2*>(&As[row * LDT + kk + 2 * t]);
                float2 hi = *reinterpret_cast<const float2*>(&As[(row + 8) * LDT + kk + 2 * t]);
                af[i][0] = __float_as_uint(lo.x);
                af[i][1] = __float_as_uint(hi.x);
                af[i][2] = __float_as_uint(lo.y);
                af[i][3] = __float_as_uint(hi.y);
            }
            uint32_t bf[4][2];
            #pragma unroll
            for (int j = 0; j < 4; j++) {
                int col = wn * 32 + j * 8 + g;
                float2 bv = *reinterpret_cast<const float2*>(&Bs[col * LDT + kk + 2 * t]);
                bf[j][0] = __float_as_uint(bv.x);
                bf[j][1] = __float_as_uint(bv.y);
            }
            #pragma unroll
            for (int i = 0; i < 4; i++)
                #pragma unroll
                for (int j = 0; j < 4; j++)
                    mma8(acc[i][j], af[i], bf[j]);
        }
        __syncthreads();
    }

    // ---- epilogue (scalar stores: ldc may be odd, e.g. V_DIM=50257) ----
    #pragma unroll
    for (int i = 0; i < 4; i++) {
        #pragma unroll
        for (int j = 0; j < 4; j++) {
            int n0 = bn + wn * 32 + j * 8 + 2 * t;
            #pragma unroll
            for (int half = 0; half < 2; half++) {
                int m = bm + wm * 64 + i * 16 + g + half * 8;
                if (m >= M) continue;
                float v0 = acc[i][j][half * 2 + 0] * alpha;
                float v1 = acc[i][j][half * 2 + 1] * alpha;
                if (bias) { v0 += bias[n0]; if (n0 + 1 < N) v1 += bias[n0 + 1]; }
                if (GELU) {
                    v0 = 0.5f * v0 * (1.0f + erff(v0 * 0.70710678118654752f));
                    v1 = 0.5f * v1 * (1.0f + erff(v1 * 0.70710678118654752f));
                }
                float* crow = C + (long)m * ldc;
                if (n0 < N)     crow[n0]     = v0;
                if (n0 + 1 < N) crow[n0 + 1] = v1;
            }
        }
    }
}

// ------------------------- launch -------------------------
extern "C" void kernel_launch(void* const* d_in, const int* in_sizes, int n_in,
                              void* d_out, int out_size) {
    (void)in_sizes; (void)n_in; (void)out_size;
    const int*   x     = (const int*)  d_in[0];
    const float* W_e   = (const float*)d_in[1];
    const float* W_p   = (const float*)d_in[2];
    const float* W_q   = (const float*)d_in[3];
    const float* W_k   = (const float*)d_in[4];
    const float* W_v   = (const float*)d_in[5];
    const float* A_lr  = (const float*)d_in[6];
    const float* B_lr  = (const float*)d_in[7];
    const float* ff_w1 = (const float*)d_in[8];
    const float* ff_w2 = (const float*)d_in[9];
    float* out = (float*)d_out;

    float *p_v, *p_bvec, *p_Q, *p_K, *p_attnT, *p_Vt, *p_f, *p_h1, *p_f2;
    cudaGetSymbolAddress((void**)&p_v,     g_v);
    cudaGetSymbolAddress((void**)&p_bvec,  g_bvec);
    cudaGetSymbolAddress((void**)&p_Q,     g_Q);
    cudaGetSymbolAddress((void**)&p_K,     g_K);
    cudaGetSymbolAddress((void**)&p_attnT, g_attnT);
    cudaGetSymbolAddress((void**)&p_Vt,    g_Vt);
    cudaGetSymbolAddress((void**)&p_f,     g_f);
    cudaGetSymbolAddress((void**)&p_h1,    g_h1);
    cudaGetSymbolAddress((void**)&p_f2,    g_f2);

    const int BIG = 1 << 30;

    zero_mean_k<<<1, 768>>>();
    {
        dim3 g(3, 64);
        colmean_k<<<g, 256>>>(W_e);
    }
    {
        long nv = (long)B_DIM * S_DIM * E_DIM;
        embed_k<<<(int)((nv + 255) / 256), 256>>>(x, W_e);
    }
    bvec_k<<<B_DIM, E_DIM>>>(B_lr);

    // Q[h] = p(1025x768) @ W_q[h](768x768)   (NN)
    {
        dim3 g((E_DIM + 127) / 128, (Q_DIM + 127) / 128, H_DIM);
        gemm_tc<false, false><<<g, 256>>>(W_p, W_q, p_Q,
            Q_DIM, E_DIM, E_DIM, E_DIM, E_DIM, E_DIM,
            0L, (long)E_DIM * E_DIM, (long)Q_DIM * E_DIM, 1, BIG,
            nullptr, 1, 1.0f, nullptr, 0L);
    }
    // K[h] = p[:-1](1024x768) @ W_k[h]       (NN)
    {
        dim3 g((E_DIM + 127) / 128, (S_DIM + 127) / 128, H_DIM);
        gemm_tc<false, false><<<g, 256>>>(W_p, W_k, p_K,
            S_DIM, E_DIM, E_DIM, E_DIM, E_DIM, E_DIM,
            0L, (long)E_DIM * E_DIM, (long)S_DIM * E_DIM, 1, BIG,
            nullptr, 1, 1.0f, nullptr, 0L);
    }
    // attnT[q, h*1024+s] = Q[h,q,:] . K[h,s,:]   (NT)
    {
        dim3 g((S_DIM + 127) / 128, (Q_DIM + 127) / 128, H_DIM);
        gemm_tc<true, false><<<g, 256>>>(p_Q, p_K, p_attnT,
            Q_DIM, S_DIM, E_DIM, E_DIM, E_DIM, H_DIM * S_DIM,
            (long)Q_DIM * E_DIM, (long)S_DIM * E_DIM, (long)S_DIM, 1, BIG,
            nullptr, 1, 1.0f, nullptr, 0L);
    }
    softmax_k<<<Q_DIM * H_DIM, 256>>>(p_attnT);

    // Vt[b,h] = A_lr[h] * v[b] @ W_v[h]      (NN), z = b*H + h
    {
        dim3 g((E_DIM + 127) / 128, (S_DIM + 127) / 128, B_DIM * H_DIM);
        gemm_tc<false, false><<<g, 256>>>(p_v, W_v, p_Vt,
            S_DIM, E_DIM, E_DIM, E_DIM, E_DIM, E_DIM,
            (long)S_DIM * E_DIM, (long)E_DIM * E_DIM, (long)S_DIM * E_DIM, H_DIM, H_DIM,
            A_lr, H_DIM, 1.0f, nullptr, 0L);
    }
    // f[b] = (attnT(1025x12288) @ Vt[b](12288x768)) / S + bvec[b]   (NN)
    {
        dim3 g((E_DIM + 127) / 128, (Q_DIM + 127) / 128, B_DIM);
        gemm_tc<false, false><<<g, 256>>>(p_attnT, p_Vt, p_f,
            Q_DIM, E_DIM, H_DIM * S_DIM, H_DIM * S_DIM, E_DIM, E_DIM,
            0L, (long)H_DIM * S_DIM * E_DIM, (long)Q_DIM * E_DIM, 1, BIG,
            nullptr, 1, 1.0f / (float)S_DIM, p_bvec, (long)E_DIM);
    }
    // h1 = gelu(f(4100x768) @ ff_w1^T)       (NT + GELU)
    {
        dim3 g(DFF_DIM / 128, (B_DIM * Q_DIM + 127) / 128, 1);
        gemm_tc<true, true><<<g, 256>>>(p_f, ff_w1, p_h1,
            B_DIM * Q_DIM, DFF_DIM, E_DIM, E_DIM, E_DIM, DFF_DIM,
            0L, 0L, 0L, 1, 1,
            nullptr, 1, 1.0f, nullptr, 0L);
    }
    // f2 = h1(4100x3072) @ ff_w2^T           (NT)
    {
        dim3 g(E_DIM / 128, (B_DIM * Q_DIM + 127) / 128, 1);
        gemm_tc<true, false><<<g, 256>>>(p_h1, ff_w2, p_f2,
            B_DIM * Q_DIM, E_DIM, DFF_DIM, DFF_DIM, DFF_DIM, E_DIM,
            0L, 0L, 0L, 1, 1,
            nullptr, 1, 1.0f, nullptr, 0L);
    }
    // logits[b] = f2[b,:1024,:] @ W_e^T      (NT), z = b
    {
        dim3 g((V_DIM + 127) / 128, (S_DIM + 127) / 128, B_DIM);
        gemm_tc<true, false><<<g, 256>>>(p_f2, W_e, out,
            S_DIM, V_DIM, E_DIM, E_DIM, E_DIM, V_DIM,
            (long)Q_DIM * E_DIM, 0L, (long)S_DIM * V_DIM, 1, 1,
            nullptr, 1, 1.0f, nullptr, 0L);
    }
}

// round 4
// speedup vs baseline: 1.6616x; 1.0067x over previous
#include <cuda_runtime.h>
#include <math.h>
#include <stdint.h>

#define E_DIM   768
#define S_DIM   1024
#define B_DIM   4
#define H_DIM   12
#define V_DIM   50257
#define DFF_DIM 3072
#define Q_DIM   1025   // S+1

// ------------------------- scratch (static device globals) -------------------------
__device__ float g_meanWe[E_DIM];
__device__ float g_v    [(long)B_DIM*S_DIM*E_DIM];
__device__ float g_bvec [B_DIM*E_DIM];
__device__ float g_Q    [(long)H_DIM*Q_DIM*E_DIM];
__device__ float g_K    [(long)H_DIM*S_DIM*E_DIM];
__device__ float g_attnT[(long)Q_DIM*H_DIM*S_DIM];           // (q, h*S+s)
__device__ float g_Vt   [(long)B_DIM*H_DIM*S_DIM*E_DIM];     // (b, h*S+s, e)
__device__ float g_f    [(long)B_DIM*Q_DIM*E_DIM];
__device__ float g_h1   [(long)B_DIM*Q_DIM*DFF_DIM];
__device__ float g_f2   [(long)B_DIM*Q_DIM*E_DIM];

// ------------------------- small kernels -------------------------
__global__ void zero_init_k() {
    int t = threadIdx.x;                         // 1024 threads
    if (t < E_DIM) g_meanWe[t] = 0.0f;
    for (int i = t; i < B_DIM * E_DIM; i += 1024) g_bvec[i] = 0.0f;
}

__global__ void colmean_k(const float* __restrict__ W_e) {
    int e = blockIdx.x * 256 + threadIdx.x;
    int chunk = blockIdx.y;
    const int CH = (V_DIM + 63) / 64;
    int v0 = chunk * CH;
    int v1 = v0 + CH; if (v1 > V_DIM) v1 = V_DIM;
    float s = 0.0f;
    for (int v = v0; v < v1; v++) s += W_e[(long)v * E_DIM + e];
    atomicAdd(&g_meanWe[e], s * (1.0f / 50257.0f));
}

__global__ void embed_k(const int* __restrict__ x, const float* __restrict__ W_e) {
    long i = (long)blockIdx.x * blockDim.x + threadIdx.x;
    const long n = (long)B_DIM * S_DIM * E_DIM;
    if (i >= n) return;
    int e = (int)(i % E_DIM);
    long bs = i / E_DIM;
    g_v[i] = W_e[(long)x[bs] * E_DIM + e] - g_meanWe[e];
}

__global__ void bvec_k(const float* __restrict__ Blr) {
    int b = blockIdx.x;
    int chunk = blockIdx.y;               // 16 chunks of 64 rows
    int e = threadIdx.x;                  // 768
    const float* vb = g_v + (long)b * S_DIM * E_DIM + (long)chunk * 64 * E_DIM + e;
    float s = 0.0f;
    #pragma unroll 4
    for (int t = 0; t < 64; t++) s += vb[(long)t * E_DIM];
    atomicAdd(&g_bvec[b * E_DIM + e], s * Blr[0] * (1.0f / (float)S_DIM));
}

__global__ void softmax_k(float* __restrict__ attnT) {
    int q = blockIdx.x / H_DIM;
    int h = blockIdx.x % H_DIM;
    float* row = attnT + (long)q * (H_DIM * S_DIM) + (long)h * S_DIM;
    int tid = threadIdx.x;
    const float scale = 0.03608439182435161f;   // 1/sqrt(768)
    float4 v = reinterpret_cast<float4*>(row)[tid];
    float m = fmaxf(fmaxf(v.x, v.y), fmaxf(v.z, v.w));
    __shared__ float red[8];
    #pragma unroll
    for (int o = 16; o > 0; o >>= 1) m = fmaxf(m, __shfl_xor_sync(0xffffffffu, m, o));
    if ((tid & 31) == 0) red[tid >> 5] = m;
    __syncthreads();
    m = red[0];
    #pragma unroll
    for (int w = 1; w < 8; w++) m = fmaxf(m, red[w]);
    float ex = expf(scale * (v.x - m));
    float ey = expf(scale * (v.y - m));
    float ez = expf(scale * (v.z - m));
    float ew = expf(scale * (v.w - m));
    float s = ex + ey + ez + ew;
    #pragma unroll
    for (int o = 16; o > 0; o >>= 1) s += __shfl_xor_sync(0xffffffffu, s, o);
    __syncthreads();
    if ((tid & 31) == 0) red[tid >> 5] = s;
    __syncthreads();
    s = 0.0f;
    #pragma unroll
    for (int w = 0; w < 8; w++) s += red[w];
    float inv = 1.0f / s;
    v.x = ex * inv; v.y = ey * inv; v.z = ez * inv; v.w = ew * inv;
    reinterpret_cast<float4*>(row)[tid] = v;
}

// ------------------------- tf32 tensor-core GEMM (pipelined) -------------------------
// C[m,n] = alpha * sum_k A[m,k] * B(k,n) (+ bias[n]) [+ exact GELU]
// BT: B is (N x K) row-major.  !BT: B is (K x N) row-major.
// ABATCH: A row m maps to A + (m>>10)*abStride + (m&1023)*lda  (batch folded into M)
// grid: x = M blocks (fast), y = N blocks, z = batch.
// Block tile 128x128x32, 8 warps (2x4), warp tile 64x32, mma.m16n8k8.tf32.
// Mainloop: register-staged prefetch of the next K-tile overlaps the MMAs.

#define LDT 40   // padded leading dim (floats)

__device__ __forceinline__ uint32_t f2tf(float f) {
    uint32_t u; asm("cvt.rna.tf32.f32 %0, %1;" : "=r"(u) : "f"(f)); return u;
}

__device__ __forceinline__ void mma8(float* c, const uint32_t* a, const uint32_t* b) {
    asm volatile("mma.sync.aligned.m16n8k8.row.col.f32.tf32.tf32.f32 "
        "{%0,%1,%2,%3}, {%4,%5,%6,%7}, {%8,%9}, {%0,%1,%2,%3};"
        : "+f"(c[0]), "+f"(c[1]), "+f"(c[2]), "+f"(c[3])
        : "r"(a[0]), "r"(a[1]), "r"(a[2]), "r"(a[3]), "r"(b[0]), "r"(b[1]));
}

template<bool BT, bool GELU, bool ABATCH>
__global__ __launch_bounds__(256, 2)
void gemm_tc(const float* __restrict__ Ag, const float* __restrict__ Bg,
             float* __restrict__ Cg,
             int M, int N, int K, int lda, int ldb, int ldc,
             long sA, long sB, long sC, int divA, int modB, long abStride,
             const float* __restrict__ alphaPtr, int alphaMod, float alphaScale,
             const float* __restrict__ biasPtr, long biasStride)
{
    __shared__ float As[128 * LDT];
    __shared__ float Bs[128 * LDT];

    int z = blockIdx.z;
    const float* A = Ag + (long)(z / divA) * sA;
    const float* B = Bg + (long)(z % modB) * sB;
    float* C = Cg + (long)z * sC;
    float alpha = alphaScale;
    if (alphaPtr) alpha *= alphaPtr[z % alphaMod];
    const float* bias = biasPtr ? (biasPtr + (long)z * biasStride) : nullptr;

    int bm = blockIdx.x * 128;
    int bn = blockIdx.y * 128;
    int tid = threadIdx.x;
    int warp = tid >> 5, lane = tid & 31;
    int wm = warp >> 2, wn = warp & 3;      // 2 x 4 warp grid
    int g = lane >> 2, t = lane & 3;

    float acc[4][4][4];
    #pragma unroll
    for (int i = 0; i < 4; i++)
        #pragma unroll
        for (int j = 0; j < 4; j++)
            #pragma unroll
            for (int r = 0; r < 4; r++) acc[i][j][r] = 0.0f;

    int arow = tid >> 1;
    int acolg = (tid & 1) << 4;
    int bkr = tid >> 3;
    int bnc = (tid & 7) << 4;

    // resolved A row pointer (handles ABATCH remap and M guard once)
    int am = bm + arow;
    bool a_ok = am < M;
    const float* arow_ptr;
    if (ABATCH) {
        arow_ptr = A + (long)(am >> 10) * abStride + (long)(am & 1023) * lda + acolg;
    } else {
        arow_ptr = A + (long)am * lda + acolg;
    }
    const float* brow_ptr = BT ? (B + (long)(bn + arow) * ldb + acolg) : nullptr;
    bool b_ok = BT ? ((bn + arow) < N) : true;

    float4 stA[4], stB[4];

    // ---- prefetch helper (reads K-tile k0 into stA/stB) ----
    auto load_tiles = [&](int k0) {
        #pragma unroll
        for (int q = 0; q < 4; q++)
            stA[q] = a_ok ? *reinterpret_cast<const float4*>(arow_ptr + k0 + q * 4)
                          : make_float4(0.f, 0.f, 0.f, 0.f);
        if (BT) {
            #pragma unroll
            for (int q = 0; q < 4; q++)
                stB[q] = b_ok ? *reinterpret_cast<const float4*>(brow_ptr + k0 + q * 4)
                              : make_float4(0.f, 0.f, 0.f, 0.f);
        } else {
            const float* src = B + (long)(k0 + bkr) * ldb + bn + bnc;
            #pragma unroll
            for (int q = 0; q < 4; q++) {
                int n = bn + bnc + q * 4;
                if (n + 3 < N) {
                    stB[q] = *reinterpret_cast<const float4*>(src + q * 4);
                } else {
                    stB[q].x = (n + 0 < N) ? src[q * 4 + 0] : 0.f;
                    stB[q].y = (n + 1 < N) ? src[q * 4 + 1] : 0.f;
                    stB[q].z = (n + 2 < N) ? src[q * 4 + 2] : 0.f;
                    stB[q].w = (n + 3 < N) ? src[q * 4 + 3] : 0.f;
                }
            }
        }
    };

    // ---- store helper (cvt + permuted STS) ----
    auto store_tiles = [&]() {
        {
            float* dst = As + arow * LDT;
            #pragma unroll
            for (int q = 0; q < 4; q++) {
                int kb = acolg + q * 4;
                int base8 = kb & 24;
                int off = (kb & 4) ? 1 : 0;
                dst[base8 + off + 0] = __uint_as_float(f2tf(stA[q].x));
                dst[base8 + off + 2] = __uint_as_float(f2tf(stA[q].y));
                dst[base8 + off + 4] = __uint_as_float(f2tf(stA[q].z));
                dst[base8 + off + 6] = __uint_as_float(f2tf(stA[q].w));
            }
        }
        if (BT) {
            float* dst = Bs + arow * LDT;
            #pragma unroll
            for (int q = 0; q < 4; q++) {
                int kb = acolg + q * 4;
                int base8 = kb & 24;
                int off = (kb & 4) ? 1 : 0;
                dst[base8 + off + 0] = __uint_as_float(f2tf(stB[q].x));
                dst[base8 + off + 2] = __uint_as_float(f2tf(stB[q].y));
                dst[base8 + off + 4] = __uint_as_float(f2tf(stB[q].z));
                dst[base8 + off + 6] = __uint_as_float(f2tf(stB[q].w));
            }
        } else {
            int base8 = bkr & 24;
            int kcol = base8 + (((bkr & 3) << 1) | ((bkr & 7) >> 2));
            #pragma unroll
            for (int q = 0; q < 4; q++) {
                int nl = bnc + q * 4;
                Bs[(nl + 0) * LDT + kcol] = __uint_as_float(f2tf(stB[q].x));
                Bs[(nl + 1) * LDT + kcol] = __uint_as_float(f2tf(stB[q].y));
                Bs[(nl + 2) * LDT + kcol] = __uint_as_float(f2tf(stB[q].z));
                Bs[(nl + 3) * LDT + kcol] = __uint_as_float(f2tf(stB[q].w));
            }
        }
    };

    int ntiles = K >> 5;   // all K are multiples of 32
    load_tiles(0);

    for (int it = 0; it < ntiles; it++) {
        store_tiles();
        __syncthreads();
        if (it + 1 < ntiles) load_tiles((it + 1) << 5);   // LDGs overlap the MMAs below

        #pragma unroll
        for (int ks = 0; ks < 4; ks++) {
            int kk = ks * 8;
            uint32_t af[4][4];
            #pragma unroll
            for (int i = 0; i < 4; i++) {
                int row = wm * 64 + i * 16 + g;
                float2 lo = *reinterpret_cast<const float2*>(&As[row * LDT + kk + 2 * t]);
                float2 hi = *reinterpret_cast<const float2*>(&As[(row + 8) * LDT + kk + 2 * t]);
                af[i][0] = __float_as_uint(lo.x);
                af[i][1] = __float_as_uint(hi.x);
                af[i][2] = __float_as_uint(lo.y);
                af[i][3] = __float_as_uint(hi.y);
            }
            uint32_t bf[4][2];
            #pragma unroll
            for (int j = 0; j < 4; j++) {
                int col = wn * 32 + j * 8 + g;
                float2 bv = *reinterpret_cast<const float2*>(&Bs[col * LDT + kk + 2 * t]);
                bf[j][0] = __float_as_uint(bv.x);
                bf[j][1] = __float_as_uint(bv.y);
            }
            #pragma unroll
            for (int i = 0; i < 4; i++)
                #pragma unroll
                for (int j = 0; j < 4; j++)
                    mma8(acc[i][j], af[i], bf[j]);
        }
        __syncthreads();
    }

    // ---- epilogue (scalar stores: ldc may be odd, e.g. V_DIM=50257) ----
    #pragma unroll
    for (int i = 0; i < 4; i++) {
        #pragma unroll
        for (int j = 0; j < 4; j++) {
            int n0 = bn + wn * 32 + j * 8 + 2 * t;
            #pragma unroll
            for (int half = 0; half < 2; half++) {
                int m = bm + wm * 64 + i * 16 + g + half * 8;
                if (m >= M) continue;
                float v0 = acc[i][j][half * 2 + 0] * alpha;
                float v1 = acc[i][j][half * 2 + 1] * alpha;
                if (bias) { v0 += bias[n0]; if (n0 + 1 < N) v1 += bias[n0 + 1]; }
                if (GELU) {
                    v0 = 0.5f * v0 * (1.0f + erff(v0 * 0.70710678118654752f));
                    v1 = 0.5f * v1 * (1.0f + erff(v1 * 0.70710678118654752f));
                }
                float* crow = C + (long)m * ldc;
                if (n0 < N)     crow[n0]     = v0;
                if (n0 + 1 < N) crow[n0 + 1] = v1;
            }
        }
    }
}

// ------------------------- launch -------------------------
extern "C" void kernel_launch(void* const* d_in, const int* in_sizes, int n_in,
                              void* d_out, int out_size) {
    (void)in_sizes; (void)n_in; (void)out_size;
    const int*   x     = (const int*)  d_in[0];
    const float* W_e   = (const float*)d_in[1];
    const float* W_p   = (const float*)d_in[2];
    const float* W_q   = (const float*)d_in[3];
    const float* W_k   = (const float*)d_in[4];
    const float* W_v   = (const float*)d_in[5];
    const float* A_lr  = (const float*)d_in[6];
    const float* B_lr  = (const float*)d_in[7];
    const float* ff_w1 = (const float*)d_in[8];
    const float* ff_w2 = (const float*)d_in[9];
    float* out = (float*)d_out;

    float *p_v, *p_bvec, *p_Q, *p_K, *p_attnT, *p_Vt, *p_f, *p_h1, *p_f2;
    cudaGetSymbolAddress((void**)&p_v,     g_v);
    cudaGetSymbolAddress((void**)&p_bvec,  g_bvec);
    cudaGetSymbolAddress((void**)&p_Q,     g_Q);
    cudaGetSymbolAddress((void**)&p_K,     g_K);
    cudaGetSymbolAddress((void**)&p_attnT, g_attnT);
    cudaGetSymbolAddress((void**)&p_Vt,    g_Vt);
    cudaGetSymbolAddress((void**)&p_f,     g_f);
    cudaGetSymbolAddress((void**)&p_h1,    g_h1);
    cudaGetSymbolAddress((void**)&p_f2,    g_f2);

    const int BIG = 1 << 30;

    zero_init_k<<<1, 1024>>>();
    {
        dim3 g(3, 64);
        colmean_k<<<g, 256>>>(W_e);
    }
    {
        long nv = (long)B_DIM * S_DIM * E_DIM;
        embed_k<<<(int)((nv + 255) / 256), 256>>>(x, W_e);
    }
    {
        dim3 g(B_DIM, 16);
        bvec_k<<<g, E_DIM>>>(B_lr);
    }

    // Q[h] = p(1025x768) @ W_q[h](768x768)   (NN)
    {
        dim3 g((Q_DIM + 127) / 128, E_DIM / 128, H_DIM);
        gemm_tc<false, false, false><<<g, 256>>>(W_p, W_q, p_Q,
            Q_DIM, E_DIM, E_DIM, E_DIM, E_DIM, E_DIM,
            0L, (long)E_DIM * E_DIM, (long)Q_DIM * E_DIM, 1, BIG, 0L,
            nullptr, 1, 1.0f, nullptr, 0L);
    }
    // K[h] = p[:-1](1024x768) @ W_k[h]       (NN)
    {
        dim3 g(S_DIM / 128, E_DIM / 128, H_DIM);
        gemm_tc<false, false, false><<<g, 256>>>(W_p, W_k, p_K,
            S_DIM, E_DIM, E_DIM, E_DIM, E_DIM, E_DIM,
            0L, (long)E_DIM * E_DIM, (long)S_DIM * E_DIM, 1, BIG, 0L,
            nullptr, 1, 1.0f, nullptr, 0L);
    }
    // attnT[q, h*1024+s] = Q[h,q,:] . K[h,s,:]   (NT)
    {
        dim3 g((Q_DIM + 127) / 128, S_DIM / 128, H_DIM);
        gemm_tc<true, false, false><<<g, 256>>>(p_Q, p_K, p_attnT,
            Q_DIM, S_DIM, E_DIM, E_DIM, E_DIM, H_DIM * S_DIM,
            (long)Q_DIM * E_DIM, (long)S_DIM * E_DIM, (long)S_DIM, 1, BIG, 0L,
            nullptr, 1, 1.0f, nullptr, 0L);
    }
    softmax_k<<<Q_DIM * H_DIM, 256>>>(p_attnT);

    // Vt[b,h] = A_lr[h] * v[b] @ W_v[h]      (NN), z = b*H + h
    {
        dim3 g(S_DIM / 128, E_DIM / 128, B_DIM * H_DIM);
        gemm_tc<false, false, false><<<g, 256>>>(p_v, W_v, p_Vt,
            S_DIM, E_DIM, E_DIM, E_DIM, E_DIM, E_DIM,
            (long)S_DIM * E_DIM, (long)E_DIM * E_DIM, (long)S_DIM * E_DIM, H_DIM, H_DIM, 0L,
            A_lr, H_DIM, 1.0f, nullptr, 0L);
    }
    // f[b] = (attnT(1025x12288) @ Vt[b](12288x768)) / S + bvec[b]   (NN)
    {
        dim3 g((Q_DIM + 127) / 128, E_DIM / 128, B_DIM);
        gemm_tc<false, false, false><<<g, 256>>>(p_attnT, p_Vt, p_f,
            Q_DIM, E_DIM, H_DIM * S_DIM, H_DIM * S_DIM, E_DIM, E_DIM,
            0L, (long)H_DIM * S_DIM * E_DIM, (long)Q_DIM * E_DIM, 1, BIG, 0L,
            nullptr, 1, 1.0f / (float)S_DIM, p_bvec, (long)E_DIM);
    }
    // h1 = gelu(f(4100x768) @ ff_w1^T)       (NT + GELU)
    {
        dim3 g((B_DIM * Q_DIM + 127) / 128, DFF_DIM / 128, 1);
        gemm_tc<true, true, false><<<g, 256>>>(p_f, ff_w1, p_h1,
            B_DIM * Q_DIM, DFF_DIM, E_DIM, E_DIM, E_DIM, DFF_DIM,
            0L, 0L, 0L, 1, 1, 0L,
            nullptr, 1, 1.0f, nullptr, 0L);
    }
    // f2 = h1(4100x3072) @ ff_w2^T           (NT)
    {
        dim3 g((B_DIM * Q_DIM + 127) / 128, E_DIM / 128, 1);
        gemm_tc<true, false, false><<<g, 256>>>(p_h1, ff_w2, p_f2,
            B_DIM * Q_DIM, E_DIM, DFF_DIM, DFF_DIM, DFF_DIM, E_DIM,
            0L, 0L, 0L, 1, 1, 0L,
            nullptr, 1, 1.0f, nullptr, 0L);
    }
    // logits: M = 4096 (batch folded, A row remap), N = 50257   (NT)
    {
        dim3 g((B_DIM * S_DIM) / 128, (V_DIM + 127) / 128, 1);
        gemm_tc<true, false, true><<<g, 256>>>(p_f2, W_e, out,
            B_DIM * S_DIM, V_DIM, E_DIM, E_DIM, E_DIM, V_DIM,
            0L, 0L, 0L, 1, 1, (long)Q_DIM * E_DIM,
            nullptr, 1, 1.0f, nullptr, 0L);
    }
}

// round 5
// speedup vs baseline: 1.8394x; 1.1070x over previous
#include <cuda_runtime.h>
#include <math.h>
#include <stdint.h>

#define E_DIM   768
#define S_DIM   1024
#define B_DIM   4
#define H_DIM   12
#define V_DIM   50257
#define DFF_DIM 3072
#define Q_DIM   1025   // S+1

// ------------------------- scratch (static device globals) -------------------------
__device__ float g_meanWe[E_DIM];
__device__ float g_v    [(long)B_DIM*S_DIM*E_DIM];
__device__ float g_bvec [B_DIM*E_DIM];
__device__ float g_WqT  [(long)H_DIM*E_DIM*E_DIM];
__device__ float g_WkT  [(long)H_DIM*E_DIM*E_DIM];
__device__ float g_WvT  [(long)H_DIM*E_DIM*E_DIM];
__device__ float g_Q    [(long)H_DIM*Q_DIM*E_DIM];
__device__ float g_K    [(long)H_DIM*S_DIM*E_DIM];
__device__ float g_attnT[(long)Q_DIM*H_DIM*S_DIM];           // (q, h*S+s)
__device__ float g_VtT  [(long)B_DIM*E_DIM*H_DIM*S_DIM];     // (b, e, h*S+s)
__device__ float g_f    [(long)B_DIM*Q_DIM*E_DIM];
__device__ float g_h1   [(long)B_DIM*Q_DIM*DFF_DIM];
__device__ float g_f2   [(long)B_DIM*Q_DIM*E_DIM];

// ------------------------- small kernels -------------------------
__global__ void zero_init_k() {
    int t = threadIdx.x;
    if (t < E_DIM) g_meanWe[t] = 0.0f;
    for (int i = t; i < B_DIM * E_DIM; i += 1024) g_bvec[i] = 0.0f;
}

__global__ void colmean_k(const float* __restrict__ W_e) {
    int e = blockIdx.x * 256 + threadIdx.x;
    int chunk = blockIdx.y;
    const int CH = (V_DIM + 63) / 64;
    int v0 = chunk * CH;
    int v1 = v0 + CH; if (v1 > V_DIM) v1 = V_DIM;
    float s = 0.0f;
    for (int v = v0; v < v1; v++) s += W_e[(long)v * E_DIM + e];
    atomicAdd(&g_meanWe[e], s * (1.0f / 50257.0f));
}

__global__ void embed_k(const int* __restrict__ x, const float* __restrict__ W_e) {
    long i = (long)blockIdx.x * blockDim.x + threadIdx.x;
    const long n = (long)B_DIM * S_DIM * E_DIM;
    if (i >= n) return;
    int e = (int)(i % E_DIM);
    long bs = i / E_DIM;
    g_v[i] = W_e[(long)x[bs] * E_DIM + e] - g_meanWe[e];
}

__global__ void bvec_k(const float* __restrict__ Blr) {
    int b = blockIdx.x;
    int chunk = blockIdx.y;               // 16 chunks of 64 rows
    int e = threadIdx.x;                  // 768
    const float* vb = g_v + (long)b * S_DIM * E_DIM + (long)chunk * 64 * E_DIM + e;
    float s = 0.0f;
    #pragma unroll 4
    for (int t = 0; t < 64; t++) s += vb[(long)t * E_DIM];
    atomicAdd(&g_bvec[b * E_DIM + e], s * Blr[0] * (1.0f / (float)S_DIM));
}

// per-head transpose: out[h][j][i] = in[h][i][j], E x E
__global__ void transpose_head_k(const float* __restrict__ in, float* __restrict__ out) {
    __shared__ float tile[32][33];
    int h = blockIdx.z;
    int i0 = blockIdx.y * 32, j0 = blockIdx.x * 32;
    const float* src = in + (long)h * E_DIM * E_DIM;
    float* dst = out + (long)h * E_DIM * E_DIM;
    int tx = threadIdx.x, ty = threadIdx.y;
    #pragma unroll
    for (int r = 0; r < 32; r += 8)
        tile[ty + r][tx] = src[(long)(i0 + ty + r) * E_DIM + j0 + tx];
    __syncthreads();
    #pragma unroll
    for (int r = 0; r < 32; r += 8)
        dst[(long)(j0 + ty + r) * E_DIM + i0 + tx] = tile[tx][ty + r];
}

__global__ void softmax_k(float* __restrict__ attnT) {
    int q = blockIdx.x / H_DIM;
    int h = blockIdx.x % H_DIM;
    float* row = attnT + (long)q * (H_DIM * S_DIM) + (long)h * S_DIM;
    int tid = threadIdx.x;
    const float scale = 0.03608439182435161f;   // 1/sqrt(768)
    float4 v = reinterpret_cast<float4*>(row)[tid];
    float m = fmaxf(fmaxf(v.x, v.y), fmaxf(v.z, v.w));
    __shared__ float red[8];
    #pragma unroll
    for (int o = 16; o > 0; o >>= 1) m = fmaxf(m, __shfl_xor_sync(0xffffffffu, m, o));
    if ((tid & 31) == 0) red[tid >> 5] = m;
    __syncthreads();
    m = red[0];
    #pragma unroll
    for (int w = 1; w < 8; w++) m = fmaxf(m, red[w]);
    float ex = expf(scale * (v.x - m));
    float ey = expf(scale * (v.y - m));
    float ez = expf(scale * (v.z - m));
    float ew = expf(scale * (v.w - m));
    float s = ex + ey + ez + ew;
    #pragma unroll
    for (int o = 16; o > 0; o >>= 1) s += __shfl_xor_sync(0xffffffffu, s, o);
    __syncthreads();
    if ((tid & 31) == 0) red[tid >> 5] = s;
    __syncthreads();
    s = 0.0f;
    #pragma unroll
    for (int w = 0; w < 8; w++) s += red[w];
    float inv = 1.0f / s;
    v.x = ex * inv; v.y = ey * inv; v.z = ez * inv; v.w = ew * inv;
    reinterpret_cast<float4*>(row)[tid] = v;
}

// ------------------------- tf32 NT GEMM, double-buffered -------------------------
// C[m,n] = alpha * sum_k A[m,k] * B[n,k] (+ bias[n]) [+ exact GELU]
// block 128x128x32, 512 threads, 16 warps (4x4), warp tile 32x32.
// smem layout per tile row (32 floats): word(k) = ((k&3)*8 + (k>>2)) ^ ((row&7)*4)
//   -> per-thread K-fragment for a row = two LDS.128, conflict-free.

__device__ __forceinline__ uint32_t f2tf(float f) {
    uint32_t u; asm("cvt.rna.tf32.f32 %0, %1;" : "=r"(u) : "f"(f)); return u;
}

__device__ __forceinline__ void mma8(float* c, uint32_t a0, uint32_t a1, uint32_t a2, uint32_t a3,
                                     uint32_t b0, uint32_t b1) {
    asm volatile("mma.sync.aligned.m16n8k8.row.col.f32.tf32.tf32.f32 "
        "{%0,%1,%2,%3}, {%4,%5,%6,%7}, {%8,%9}, {%0,%1,%2,%3};"
        : "+f"(c[0]), "+f"(c[1]), "+f"(c[2]), "+f"(c[3])
        : "r"(a0), "r"(a1), "r"(a2), "r"(a3), "r"(b0), "r"(b1));
}

__device__ __forceinline__ void sts_quad(float* buf, int row, int q, float4 v) {
    float* d = buf + row * 32;
    int c = (row & 7) * 4;
    d[(q     ) ^ c] = __uint_as_float(f2tf(v.x));
    d[(8  + q) ^ c] = __uint_as_float(f2tf(v.y));
    d[(16 + q) ^ c] = __uint_as_float(f2tf(v.z));
    d[(24 + q) ^ c] = __uint_as_float(f2tf(v.w));
}

#define GEMM_SMEM 65536

template<bool GELU, bool ABATCH>
__global__ __launch_bounds__(512, 1)
void gemm_nt(const float* __restrict__ Ag, const float* __restrict__ Bg,
             float* __restrict__ Cg,
             int M, int N, int K, int lda, int ldb, int ldc,
             long sA, long sB, long sC1, long sC2, int divA, int modB, long abStride,
             const float* __restrict__ alphaPtr, int alphaMod, float alphaScale,
             const float* __restrict__ biasPtr, long biasStride)
{
    extern __shared__ float sm[];      // [2 stages][As 4096 | Bs 4096]
    float* Asb[2] = { sm,        sm + 8192 };
    float* Bsb[2] = { sm + 4096, sm + 12288 };

    int z = blockIdx.z;
    const float* A = Ag + (long)(z / divA) * sA;
    const float* B = Bg + (long)(z % modB) * sB;
    float* C = Cg + (long)(z / divA) * sC1 + (long)(z % modB) * sC2;
    float alpha = alphaScale;
    if (alphaPtr) alpha *= alphaPtr[(z / divA) % alphaMod];
    const float* bias = biasPtr ? (biasPtr + (long)z * biasStride) : nullptr;

    int bm = blockIdx.x * 128;
    int bn = blockIdx.y * 128;
    int tid = threadIdx.x;
    int warp = tid >> 5, lane = tid & 31;
    int wm = warp >> 2, wn = warp & 3;     // 4x4 warp grid
    int g = lane >> 2, t = lane & 3;

    // loader: thread covers rows lrow and lrow+64, quad lq (k = lq*4..lq*4+3)
    int lrow = tid >> 3;
    int lq = tid & 7;
    int am0 = bm + lrow, am1 = am0 + 64;
    const float *aptr0, *aptr1;
    if (ABATCH) {
        aptr0 = A + (long)(am0 >> 10) * abStride + (long)(am0 & 1023) * lda + lq * 4;
        aptr1 = A + (long)(am1 >> 10) * abStride + (long)(am1 & 1023) * lda + lq * 4;
    } else {
        aptr0 = A + (long)am0 * lda + lq * 4;
        aptr1 = A + (long)am1 * lda + lq * 4;
    }
    bool aok0 = am0 < M, aok1 = am1 < M;
    int nr0 = bn + lrow, nr1 = nr0 + 64;
    const float* bptr0 = B + (long)nr0 * ldb + lq * 4;
    const float* bptr1 = B + (long)nr1 * ldb + lq * 4;
    bool bok0 = nr0 < N, bok1 = nr1 < N;

    float acc[2][4][4];
    #pragma unroll
    for (int i = 0; i < 2; i++)
        #pragma unroll
        for (int j = 0; j < 4; j++)
            #pragma unroll
            for (int r = 0; r < 4; r++) acc[i][j][r] = 0.0f;

    const float4 zero4 = make_float4(0.f, 0.f, 0.f, 0.f);
    float4 rA0, rA1, rB0, rB1;

    rA0 = aok0 ? *reinterpret_cast<const float4*>(aptr0) : zero4;
    rA1 = aok1 ? *reinterpret_cast<const float4*>(aptr1) : zero4;
    rB0 = bok0 ? *reinterpret_cast<const float4*>(bptr0) : zero4;
    rB1 = bok1 ? *reinterpret_cast<const float4*>(bptr1) : zero4;
    sts_quad(Asb[0], lrow, lq, rA0);
    sts_quad(Asb[0], lrow + 64, lq, rA1);
    sts_quad(Bsb[0], lrow, lq, rB0);
    sts_quad(Bsb[0], lrow + 64, lq, rB1);
    __syncthreads();

    int nt = K >> 5;
    for (int it = 0; it < nt; it++) {
        int cur = it & 1;
        bool more = (it + 1) < nt;
        if (more) {
            int k0 = (it + 1) << 5;
            rA0 = aok0 ? *reinterpret_cast<const float4*>(aptr0 + k0) : zero4;
            rA1 = aok1 ? *reinterpret_cast<const float4*>(aptr1 + k0) : zero4;
            rB0 = bok0 ? *reinterpret_cast<const float4*>(bptr0 + k0) : zero4;
            rB1 = bok1 ? *reinterpret_cast<const float4*>(bptr1 + k0) : zero4;
        }

        const float* As = Asb[cur];
        const float* Bs = Bsb[cur];

        // B fragments for whole 32-K tile: 8 x LDS.128
        float4 b4[4][2];
        #pragma unroll
        for (int j = 0; j < 4; j++) {
            int cr = wn * 32 + j * 8 + g;
            int base = cr * 32;
            int cx = (cr & 7) * 4;
            b4[j][0] = *reinterpret_cast<const float4*>(&Bs[base + ((t * 8) ^ cx)]);
            b4[j][1] = *reinterpret_cast<const float4*>(&Bs[base + ((t * 8 + 4) ^ cx)]);
        }

        #pragma unroll
        for (int i = 0; i < 2; i++) {
            int ra = wm * 32 + i * 16 + g;
            int rb = ra + 8;
            int cxa = (ra & 7) * 4, cxb = (rb & 7) * 4;
            float4 aA0 = *reinterpret_cast<const float4*>(&As[ra * 32 + ((t * 8) ^ cxa)]);
            float4 aA1 = *reinterpret_cast<const float4*>(&As[ra * 32 + ((t * 8 + 4) ^ cxa)]);
            float4 aB0 = *reinterpret_cast<const float4*>(&As[rb * 32 + ((t * 8) ^ cxb)]);
            float4 aB1 = *reinterpret_cast<const float4*>(&As[rb * 32 + ((t * 8 + 4) ^ cxb)]);
            #pragma unroll
            for (int j = 0; j < 4; j++) {
                mma8(acc[i][j], __float_as_uint(aA0.x), __float_as_uint(aB0.x),
                                __float_as_uint(aA0.y), __float_as_uint(aB0.y),
                                __float_as_uint(b4[j][0].x), __float_as_uint(b4[j][0].y));
                mma8(acc[i][j], __float_as_uint(aA0.z), __float_as_uint(aB0.z),
                                __float_as_uint(aA0.w), __float_as_uint(aB0.w),
                                __float_as_uint(b4[j][0].z), __float_as_uint(b4[j][0].w));
                mma8(acc[i][j], __float_as_uint(aA1.x), __float_as_uint(aB1.x),
                                __float_as_uint(aA1.y), __float_as_uint(aB1.y),
                                __float_as_uint(b4[j][1].x), __float_as_uint(b4[j][1].y));
                mma8(acc[i][j], __float_as_uint(aA1.z), __float_as_uint(aB1.z),
                                __float_as_uint(aA1.w), __float_as_uint(aB1.w),
                                __float_as_uint(b4[j][1].z), __float_as_uint(b4[j][1].w));
            }
        }

        if (more) {
            int nxt = cur ^ 1;
            sts_quad(Asb[nxt], lrow, lq, rA0);
            sts_quad(Asb[nxt], lrow + 64, lq, rA1);
            sts_quad(Bsb[nxt], lrow, lq, rB0);
            sts_quad(Bsb[nxt], lrow + 64, lq, rB1);
        }
        __syncthreads();
    }

    // ---- epilogue (scalar stores: ldc may be odd) ----
    #pragma unroll
    for (int i = 0; i < 2; i++) {
        #pragma unroll
        for (int j = 0; j < 4; j++) {
            int n0 = bn + wn * 32 + j * 8 + 2 * t;
            #pragma unroll
            for (int half = 0; half < 2; half++) {
                int m = bm + wm * 32 + i * 16 + g + half * 8;
                if (m >= M) continue;
                float v0 = acc[i][j][half * 2 + 0] * alpha;
                float v1 = acc[i][j][half * 2 + 1] * alpha;
                if (bias) { v0 += bias[n0]; if (n0 + 1 < N) v1 += bias[n0 + 1]; }
                if (GELU) {
                    v0 = 0.5f * v0 * (1.0f + erff(v0 * 0.70710678118654752f));
                    v1 = 0.5f * v1 * (1.0f + erff(v1 * 0.70710678118654752f));
                }
                float* crow = C + (long)m * ldc;
                if (n0 < N)     crow[n0]     = v0;
                if (n0 + 1 < N) crow[n0 + 1] = v1;
            }
        }
    }
}

// ------------------------- launch -------------------------
extern "C" void kernel_launch(void* const* d_in, const int* in_sizes, int n_in,
                              void* d_out, int out_size) {
    (void)in_sizes; (void)n_in; (void)out_size;
    const int*   x     = (const int*)  d_in[0];
    const float* W_e   = (const float*)d_in[1];
    const float* W_p   = (const float*)d_in[2];
    const float* W_q   = (const float*)d_in[3];
    const float* W_k   = (const float*)d_in[4];
    const float* W_v   = (const float*)d_in[5];
    const float* A_lr  = (const float*)d_in[6];
    const float* B_lr  = (const float*)d_in[7];
    const float* ff_w1 = (const float*)d_in[8];
    const float* ff_w2 = (const float*)d_in[9];
    float* out = (float*)d_out;

    float *p_v, *p_bvec, *p_WqT, *p_WkT, *p_WvT, *p_Q, *p_K, *p_attnT, *p_VtT, *p_f, *p_h1, *p_f2;
    cudaGetSymbolAddress((void**)&p_v,     g_v);
    cudaGetSymbolAddress((void**)&p_bvec,  g_bvec);
    cudaGetSymbolAddress((void**)&p_WqT,   g_WqT);
    cudaGetSymbolAddress((void**)&p_WkT,   g_WkT);
    cudaGetSymbolAddress((void**)&p_WvT,   g_WvT);
    cudaGetSymbolAddress((void**)&p_Q,     g_Q);
    cudaGetSymbolAddress((void**)&p_K,     g_K);
    cudaGetSymbolAddress((void**)&p_attnT, g_attnT);
    cudaGetSymbolAddress((void**)&p_VtT,   g_VtT);
    cudaGetSymbolAddress((void**)&p_f,     g_f);
    cudaGetSymbolAddress((void**)&p_h1,    g_h1);
    cudaGetSymbolAddress((void**)&p_f2,    g_f2);

    static bool attr_done = false;
    if (!attr_done) {
        cudaFuncSetAttribute(gemm_nt<false, false>, cudaFuncAttributeMaxDynamicSharedMemorySize, GEMM_SMEM);
        cudaFuncSetAttribute(gemm_nt<true,  false>, cudaFuncAttributeMaxDynamicSharedMemorySize, GEMM_SMEM);
        cudaFuncSetAttribute(gemm_nt<false, true >, cudaFuncAttributeMaxDynamicSharedMemorySize, GEMM_SMEM);
        attr_done = true;
    }

    const int BIG = 1 << 30;
    const long EE = (long)E_DIM * E_DIM;
    const long HS = (long)H_DIM * S_DIM;   // 12288

    zero_init_k<<<1, 1024>>>();
    { dim3 g(3, 64); colmean_k<<<g, 256>>>(W_e); }
    { long nv = (long)B_DIM * S_DIM * E_DIM;
      embed_k<<<(int)((nv + 255) / 256), 256>>>(x, W_e); }
    { dim3 g(B_DIM, 16); bvec_k<<<g, E_DIM>>>(B_lr); }

    // transpose weights per head
    { dim3 g(24, 24, 12), b(32, 8);
      transpose_head_k<<<g, b>>>(W_q, p_WqT);
      transpose_head_k<<<g, b>>>(W_k, p_WkT);
      transpose_head_k<<<g, b>>>(W_v, p_WvT); }

    // Q[h] = W_p(1025x768) @ WqT[h]^T
    { dim3 g(9, 6, H_DIM);
      gemm_nt<false, false><<<g, 512, GEMM_SMEM>>>(W_p, p_WqT, p_Q,
          Q_DIM, E_DIM, E_DIM, E_DIM, E_DIM, E_DIM,
          0L, EE, (long)Q_DIM * E_DIM, 0L, 1, BIG, 0L,
          nullptr, 1, 1.0f, nullptr, 0L); }
    // K[h] = W_p[:1024] @ WkT[h]^T
    { dim3 g(8, 6, H_DIM);
      gemm_nt<false, false><<<g, 512, GEMM_SMEM>>>(W_p, p_WkT, p_K,
          S_DIM, E_DIM, E_DIM, E_DIM, E_DIM, E_DIM,
          0L, EE, (long)S_DIM * E_DIM, 0L, 1, BIG, 0L,
          nullptr, 1, 1.0f, nullptr, 0L); }
    // attnT[q, h*S+s] = Q[h] @ K[h]^T
    { dim3 g(9, 8, H_DIM);
      gemm_nt<false, false><<<g, 512, GEMM_SMEM>>>(p_Q, p_K, p_attnT,
          Q_DIM, S_DIM, E_DIM, E_DIM, E_DIM, (int)HS,
          (long)Q_DIM * E_DIM, (long)S_DIM * E_DIM, (long)S_DIM, 0L, 1, BIG, 0L,
          nullptr, 1, 1.0f, nullptr, 0L); }
    softmax_k<<<Q_DIM * H_DIM, 256>>>(p_attnT);

    // VtT[b][e][h*S+s] = A_lr[h] * (WvT[h] @ v[b]^T);  z = h*B + b
    { dim3 g(6, 8, H_DIM * B_DIM);
      gemm_nt<false, false><<<g, 512, GEMM_SMEM>>>(p_WvT, p_v, p_VtT,
          E_DIM, S_DIM, E_DIM, E_DIM, E_DIM, (int)HS,
          EE, (long)S_DIM * E_DIM, (long)S_DIM, (long)E_DIM * HS, B_DIM, B_DIM, 0L,
          A_lr, H_DIM, 1.0f, nullptr, 0L); }
    // f[b] = attnT(1025x12288) @ VtT[b]^T / S + bvec[b]
    { dim3 g(9, 6, B_DIM);
      gemm_nt<false, false><<<g, 512, GEMM_SMEM>>>(p_attnT, p_VtT, p_f,
          Q_DIM, E_DIM, (int)HS, (int)HS, (int)HS, E_DIM,
          0L, (long)E_DIM * HS, (long)Q_DIM * E_DIM, 0L, 1, BIG, 0L,
          nullptr, 1, 1.0f / (float)S_DIM, p_bvec, (long)E_DIM); }
    // h1 = gelu(f(4100x768) @ ff_w1^T)
    { dim3 g(33, 24, 1);
      gemm_nt<true, false><<<g, 512, GEMM_SMEM>>>(p_f, ff_w1, p_h1,
          B_DIM * Q_DIM, DFF_DIM, E_DIM, E_DIM, E_DIM, DFF_DIM,
          0L, 0L, 0L, 0L, 1, BIG, 0L,
          nullptr, 1, 1.0f, nullptr, 0L); }
    // f2 = h1(4100x3072) @ ff_w2^T
    { dim3 g(33, 6, 1);
      gemm_nt<false, false><<<g, 512, GEMM_SMEM>>>(p_h1, ff_w2, p_f2,
          B_DIM * Q_DIM, E_DIM, DFF_DIM, DFF_DIM, DFF_DIM, E_DIM,
          0L, 0L, 0L, 0L, 1, BIG, 0L,
          nullptr, 1, 1.0f, nullptr, 0L); }
    // logits: M=4096 (batch folded via row remap), N=50257
    { dim3 g(32, 393, 1);
      gemm_nt<false, true><<<g, 512, GEMM_SMEM>>>(p_f2, W_e, out,
          B_DIM * S_DIM, V_DIM, E_DIM, E_DIM, E_DIM, V_DIM,
          0L, 0L, 0L, 0L, 1, BIG, (long)Q_DIM * E_DIM,
          nullptr, 1, 1.0f, nullptr, 0L); }
}

// round 7
// speedup vs baseline: 1.9667x; 1.0692x over previous
#include <cuda_runtime.h>
#include <math.h>
#include <stdint.h>

#define E_DIM   768
#define S_DIM   1024
#define B_DIM   4
#define H_DIM   12
#define V_DIM   50257
#define DFF_DIM 3072
#define Q_DIM   1025   // S+1

// ------------------------- scratch (static device globals) -------------------------
__device__ float g_meanWe[E_DIM];
__device__ float g_v    [(long)B_DIM*S_DIM*E_DIM];
__device__ float g_bvec [B_DIM*E_DIM];
__device__ float g_WeR  [(long)V_DIM*E_DIM];                 // tf32-rounded W_e
__device__ float g_WpR  [(long)1152*E_DIM];                  // tf32-rounded W_p rows 0..1151
__device__ float g_w1R  [(long)DFF_DIM*E_DIM];
__device__ float g_w2R  [(long)E_DIM*DFF_DIM];
__device__ float g_WqT  [(long)H_DIM*E_DIM*E_DIM];
__device__ float g_WkT  [(long)H_DIM*E_DIM*E_DIM];
__device__ float g_WvT  [(long)H_DIM*E_DIM*E_DIM];
__device__ float g_Q    [(long)H_DIM*Q_DIM*E_DIM];
__device__ float g_K    [(long)H_DIM*S_DIM*E_DIM];
__device__ float g_attnT[(long)Q_DIM*H_DIM*S_DIM];           // (q, h*S+s)
__device__ float g_VtT  [(long)B_DIM*E_DIM*H_DIM*S_DIM];     // (b, e, h*S+s)
__device__ float g_f    [(long)B_DIM*Q_DIM*E_DIM];
__device__ float g_h1   [(long)B_DIM*Q_DIM*DFF_DIM];
__device__ float g_f2   [(long)B_DIM*Q_DIM*E_DIM];

// ------------------------- helpers -------------------------
__device__ __forceinline__ uint32_t f2tf(float f) {
    uint32_t u; asm("cvt.rna.tf32.f32 %0, %1;" : "=r"(u) : "f"(f)); return u;
}
__device__ __forceinline__ float rna(float f) { return __uint_as_float(f2tf(f)); }

__device__ __forceinline__ uint32_t s2u(const void* p) {
    uint32_t a;
    asm("{ .reg .u64 t; cvta.to.shared.u64 t, %1; cvt.u32.u64 %0, t; }" : "=r"(a) : "l"(p));
    return a;
}
__device__ __forceinline__ void cpa16(uint32_t dst, const float* src, int szbytes) {
    asm volatile("cp.async.cg.shared.global [%0], [%1], 16, %2;" :: "r"(dst), "l"(src), "r"(szbytes));
}
#define CP_COMMIT()  asm volatile("cp.async.commit_group;" ::: "memory")
#define CP_WAIT(n)   asm volatile("cp.async.wait_group %0;" :: "n"(n) : "memory")

__device__ __forceinline__ void mma8(float* c, uint32_t a0, uint32_t a1, uint32_t a2, uint32_t a3,
                                     uint32_t b0, uint32_t b1) {
    asm volatile("mma.sync.aligned.m16n8k8.row.col.f32.tf32.tf32.f32 "
        "{%0,%1,%2,%3}, {%4,%5,%6,%7}, {%8,%9}, {%0,%1,%2,%3};"
        : "+f"(c[0]), "+f"(c[1]), "+f"(c[2]), "+f"(c[3])
        : "r"(a0), "r"(a1), "r"(a2), "r"(a3), "r"(b0), "r"(b1));
}

// ------------------------- small kernels -------------------------
__global__ void zero_init_k() {
    int t = threadIdx.x;
    if (t < E_DIM) g_meanWe[t] = 0.0f;
    for (int i = t; i < B_DIM * E_DIM; i += 1024) g_bvec[i] = 0.0f;
}

__global__ void colmean_k(const float* __restrict__ W_e) {
    int e = blockIdx.x * 256 + threadIdx.x;
    int chunk = blockIdx.y;
    const int CH = (V_DIM + 63) / 64;
    int v0 = chunk * CH;
    int v1 = v0 + CH; if (v1 > V_DIM) v1 = V_DIM;
    float s = 0.0f;
    for (int v = v0; v < v1; v++) s += W_e[(long)v * E_DIM + e];
    atomicAdd(&g_meanWe[e], s * (1.0f / 50257.0f));
}

__global__ void embed_k(const int* __restrict__ x, const float* __restrict__ W_e) {
    long i = (long)blockIdx.x * blockDim.x + threadIdx.x;
    const long n = (long)B_DIM * S_DIM * E_DIM;
    if (i >= n) return;
    int e = (int)(i % E_DIM);
    long bs = i / E_DIM;
    g_v[i] = rna(W_e[(long)x[bs] * E_DIM + e] - g_meanWe[e]);
}

__global__ void bvec_k(const float* __restrict__ Blr) {
    int b = blockIdx.x;
    int chunk = blockIdx.y;
    int e = threadIdx.x;
    const float* vb = g_v + (long)b * S_DIM * E_DIM + (long)chunk * 64 * E_DIM + e;
    float s = 0.0f;
    #pragma unroll 4
    for (int t = 0; t < 64; t++) s += vb[(long)t * E_DIM];
    atomicAdd(&g_bvec[b * E_DIM + e], s * Blr[0] * (1.0f / (float)S_DIM));
}

__global__ void round_copy_k(const float4* __restrict__ s, float4* __restrict__ d, long n4) {
    long i = (long)blockIdx.x * blockDim.x + threadIdx.x;
    long stride = (long)gridDim.x * blockDim.x;
    for (; i < n4; i += stride) {
        float4 v = s[i];
        v.x = rna(v.x); v.y = rna(v.y); v.z = rna(v.z); v.w = rna(v.w);
        d[i] = v;
    }
}

// per-head transpose with tf32 rounding: out[h][j][i] = rna(in[h][i][j])
__global__ void transpose_head_k(const float* __restrict__ in, float* __restrict__ out) {
    __shared__ float tile[32][33];
    int h = blockIdx.z;
    int i0 = blockIdx.y * 32, j0 = blockIdx.x * 32;
    const float* src = in + (long)h * E_DIM * E_DIM;
    float* dst = out + (long)h * E_DIM * E_DIM;
    int tx = threadIdx.x, ty = threadIdx.y;
    #pragma unroll
    for (int r = 0; r < 32; r += 8)
        tile[ty + r][tx] = src[(long)(i0 + ty + r) * E_DIM + j0 + tx];
    __syncthreads();
    #pragma unroll
    for (int r = 0; r < 32; r += 8)
        dst[(long)(j0 + ty + r) * E_DIM + i0 + tx] = rna(tile[tx][ty + r]);
}

__global__ void softmax_k(float* __restrict__ attnT) {
    int q = blockIdx.x / H_DIM;
    int h = blockIdx.x % H_DIM;
    float* row = attnT + (long)q * (H_DIM * S_DIM) + (long)h * S_DIM;
    int tid = threadIdx.x;
    const float scale = 0.03608439182435161f;   // 1/sqrt(768)
    float4 v = reinterpret_cast<float4*>(row)[tid];
    float m = fmaxf(fmaxf(v.x, v.y), fmaxf(v.z, v.w));
    __shared__ float red[8];
    #pragma unroll
    for (int o = 16; o > 0; o >>= 1) m = fmaxf(m, __shfl_xor_sync(0xffffffffu, m, o));
    if ((tid & 31) == 0) red[tid >> 5] = m;
    __syncthreads();
    m = red[0];
    #pragma unroll
    for (int w = 1; w < 8; w++) m = fmaxf(m, red[w]);
    float ex = expf(scale * (v.x - m));
    float ey = expf(scale * (v.y - m));
    float ez = expf(scale * (v.z - m));
    float ew = expf(scale * (v.w - m));
    float s = ex + ey + ez + ew;
    #pragma unroll
    for (int o = 16; o > 0; o >>= 1) s += __shfl_xor_sync(0xffffffffu, s, o);
    __syncthreads();
    if ((tid & 31) == 0) red[tid >> 5] = s;
    __syncthreads();
    s = 0.0f;
    #pragma unroll
    for (int w = 0; w < 8; w++) s += red[w];
    float inv = 1.0f / s;
    v.x = rna(ex * inv); v.y = rna(ey * inv); v.z = rna(ez * inv); v.w = rna(ew * inv);
    reinterpret_cast<float4*>(row)[tid] = v;
}

// ------------------------- cp.async tf32 NT GEMM -------------------------
// C[m,n] = alpha * sum_k A[m,k] * B[n,k] (+ bias[n]) [+ GELU] [+ tf32 round]
// Operands are PRE-ROUNDED to tf32 in gmem, so mma.sync's bit-truncation is exact.
// Tile 128x128x32, 512 threads, 16 warps (4x4), warp tile 32x32.
// NS=4 cp.async stages, 32KB each; SW128 16B-chunk swizzle:
//   chunk c of row r stored at byte r*128 + (c ^ (r&7))*16.
// Fragment loads: scalar LDS.32, bank = ((2ks^g)*4+t) mod 32 -> conflict-free.

#define NS 4
#define STAGE_FLOATS 8192           // 32KB: A 128x32 | B 128x32
#define GEMMC_SMEM (NS * STAGE_FLOATS * 4)

template<bool GELU, bool ROUND, bool ABATCH>
__global__ __launch_bounds__(512, 1)
void gemm_cp(const float* __restrict__ Ag, const float* __restrict__ Bg,
             float* __restrict__ Cg,
             int M, int N, int K, int lda, int ldb, int ldc,
             long sA, long sB, long sC1, long sC2, int divA, int modB, long abStride,
             const float* __restrict__ alphaPtr, int alphaMod, float alphaScale,
             const float* __restrict__ biasPtr, long biasStride)
{
    extern __shared__ float sm[];    // NS stages: [A 4096][B 4096]

    int z = blockIdx.z;
    const float* A = Ag + (long)(z / divA) * sA;
    const float* B = Bg + (long)(z % modB) * sB;
    float* C = Cg + (long)(z / divA) * sC1 + (long)(z % modB) * sC2;
    float alpha = alphaScale;
    if (alphaPtr) alpha *= alphaPtr[(z / divA) % alphaMod];
    const float* bias = biasPtr ? (biasPtr + (long)z * biasStride) : nullptr;

    int bm = blockIdx.x * 128;
    int bn = blockIdx.y * 128;
    int tid = threadIdx.x;
    int warp = tid >> 5, lane = tid & 31;
    int wm = warp >> 2, wn = warp & 3;     // 4x4 warp grid
    int g = lane >> 2, t = lane & 3;

    // producer mapping: row = tid>>2 (0..127), chunks lc and lc+4
    int lrow = tid >> 2;
    int lc = tid & 3;
    int am = bm + lrow;
    bool aok = am < M;
    const float* abase;
    if (ABATCH) abase = aok ? (A + (long)(am >> 10) * abStride + (long)(am & 1023) * lda) : A;
    else        abase = aok ? (A + (long)am * lda) : A;
    int nn = bn + lrow;
    bool bok = nn < N;
    const float* bbase = bok ? (B + (long)nn * ldb) : B;
    int asz = aok ? 16 : 0, bsz = bok ? 16 : 0;

    uint32_t smb = s2u(sm);
    int rx = lrow & 7;
    uint32_t dA0 = smb + lrow * 128 + ((lc     ^ rx) << 4);
    uint32_t dA1 = smb + lrow * 128 + (((lc+4) ^ rx) << 4);
    uint32_t dB0 = dA0 + 16384;
    uint32_t dB1 = dA1 + 16384;

    float acc[2][4][4];
    #pragma unroll
    for (int i = 0; i < 2; i++)
        #pragma unroll
        for (int j = 0; j < 4; j++)
            #pragma unroll
            for (int r = 0; r < 4; r++) acc[i][j][r] = 0.0f;

    int nt = K >> 5;

    // prologue: tiles 0 .. NS-2
    #pragma unroll
    for (int p = 0; p < NS - 1; p++) {
        uint32_t off = p * (STAGE_FLOATS * 4);
        int k0 = p * 32;
        cpa16(dA0 + off, abase + k0 + lc * 4,      asz);
        cpa16(dA1 + off, abase + k0 + lc * 4 + 16, asz);
        cpa16(dB0 + off, bbase + k0 + lc * 4,      bsz);
        cpa16(dB1 + off, bbase + k0 + lc * 4 + 16, bsz);
        CP_COMMIT();
    }

    // A/B read bases for this warp (row-scaled later)
    for (int it = 0; it < nt; it++) {
        int s = it & (NS - 1);
        CP_WAIT(NS - 2);
        __syncthreads();

        int T = it + NS - 1;
        if (T < nt) {
            uint32_t off = (T & (NS - 1)) * (STAGE_FLOATS * 4);
            int k0 = T << 5;
            cpa16(dA0 + off, abase + k0 + lc * 4,      asz);
            cpa16(dA1 + off, abase + k0 + lc * 4 + 16, asz);
            cpa16(dB0 + off, bbase + k0 + lc * 4,      bsz);
            cpa16(dB1 + off, bbase + k0 + lc * 4 + 16, bsz);
        }
        CP_COMMIT();

        const float* As = sm + s * STAGE_FLOATS;
        const float* Bs = As + 4096;

        #pragma unroll
        for (int ks = 0; ks < 4; ks++) {
            // A fragments: rows wm*32 + i*16 + g (+8), k = ks*8 + t (+4)
            uint32_t af[2][4];
            #pragma unroll
            for (int i = 0; i < 2; i++) {
                int ra = wm * 32 + i * 16 + g;
                int rb = ra + 8;
                int ca = ((2 * ks) ^ (ra & 7)) * 4 + t;
                int ca4 = ((2 * ks + 1) ^ (ra & 7)) * 4 + t;
                int cb = ((2 * ks) ^ (rb & 7)) * 4 + t;
                int cb4 = ((2 * ks + 1) ^ (rb & 7)) * 4 + t;
                af[i][0] = __float_as_uint(As[ra * 32 + ca]);
                af[i][1] = __float_as_uint(As[rb * 32 + cb]);
                af[i][2] = __float_as_uint(As[ra * 32 + ca4]);
                af[i][3] = __float_as_uint(As[rb * 32 + cb4]);
            }
            uint32_t bf[4][2];
            #pragma unroll
            for (int j = 0; j < 4; j++) {
                int cb = wn * 32 + j * 8 + g;
                int c0 = ((2 * ks) ^ (cb & 7)) * 4 + t;
                int c1 = ((2 * ks + 1) ^ (cb & 7)) * 4 + t;
                bf[j][0] = __float_as_uint(Bs[cb * 32 + c0]);
                bf[j][1] = __float_as_uint(Bs[cb * 32 + c1]);
            }
            #pragma unroll
            for (int i = 0; i < 2; i++)
                #pragma unroll
                for (int j = 0; j < 4; j++)
                    mma8(acc[i][j], af[i][0], af[i][1], af[i][2], af[i][3],
                         bf[j][0], bf[j][1]);
        }
        __syncthreads();
    }

    // ---- epilogue (scalar stores; ldc may be odd) ----
    #pragma unroll
    for (int i = 0; i < 2; i++) {
        #pragma unroll
        for (int j = 0; j < 4; j++) {
            int n0 = bn + wn * 32 + j * 8 + 2 * t;
            #pragma unroll
            for (int half = 0; half < 2; half++) {
                int m = bm + wm * 32 + i * 16 + g + half * 8;
                if (m >= M) continue;
                float v0 = acc[i][j][half * 2 + 0] * alpha;
                float v1 = acc[i][j][half * 2 + 1] * alpha;
                if (bias) { v0 += bias[n0]; if (n0 + 1 < N) v1 += bias[n0 + 1]; }
                if (GELU) {
                    v0 = 0.5f * v0 * (1.0f + erff(v0 * 0.70710678118654752f));
                    v1 = 0.5f * v1 * (1.0f + erff(v1 * 0.70710678118654752f));
                }
                if (ROUND) { v0 = rna(v0); v1 = rna(v1); }
                float* crow = C + (long)m * ldc;
                if (n0 < N)     crow[n0]     = v0;
                if (n0 + 1 < N) crow[n0 + 1] = v1;
            }
        }
    }
}

// ------------------------- launch -------------------------
extern "C" void kernel_launch(void* const* d_in, const int* in_sizes, int n_in,
                              void* d_out, int out_size) {
    (void)in_sizes; (void)n_in; (void)out_size;
    const int*   x     = (const int*)  d_in[0];
    const float* W_e   = (const float*)d_in[1];
    const float* W_p   = (const float*)d_in[2];
    const float* W_q   = (const float*)d_in[3];
    const float* W_k   = (const float*)d_in[4];
    const float* W_v   = (const float*)d_in[5];
    const float* A_lr  = (const float*)d_in[6];
    const float* B_lr  = (const float*)d_in[7];
    const float* ff_w1 = (const float*)d_in[8];
    const float* ff_w2 = (const float*)d_in[9];
    float* out = (float*)d_out;

    float *p_v, *p_bvec, *p_WeR, *p_WpR, *p_w1R, *p_w2R;
    float *p_WqT, *p_WkT, *p_WvT, *p_Q, *p_K, *p_attnT, *p_VtT, *p_f, *p_h1, *p_f2;
    cudaGetSymbolAddress((void**)&p_v,     g_v);
    cudaGetSymbolAddress((void**)&p_bvec,  g_bvec);
    cudaGetSymbolAddress((void**)&p_WeR,   g_WeR);
    cudaGetSymbolAddress((void**)&p_WpR,   g_WpR);
    cudaGetSymbolAddress((void**)&p_w1R,   g_w1R);
    cudaGetSymbolAddress((void**)&p_w2R,   g_w2R);
    cudaGetSymbolAddress((void**)&p_WqT,   g_WqT);
    cudaGetSymbolAddress((void**)&p_WkT,   g_WkT);
    cudaGetSymbolAddress((void**)&p_WvT,   g_WvT);
    cudaGetSymbolAddress((void**)&p_Q,     g_Q);
    cudaGetSymbolAddress((void**)&p_K,     g_K);
    cudaGetSymbolAddress((void**)&p_attnT, g_attnT);
    cudaGetSymbolAddress((void**)&p_VtT,   g_VtT);
    cudaGetSymbolAddress((void**)&p_f,     g_f);
    cudaGetSymbolAddress((void**)&p_h1,    g_h1);
    cudaGetSymbolAddress((void**)&p_f2,    g_f2);

    static bool attr_done = false;
    if (!attr_done) {
        cudaFuncSetAttribute(gemm_cp<false, true,  false>, cudaFuncAttributeMaxDynamicSharedMemorySize, GEMMC_SMEM);
        cudaFuncSetAttribute(gemm_cp<false, false, false>, cudaFuncAttributeMaxDynamicSharedMemorySize, GEMMC_SMEM);
        cudaFuncSetAttribute(gemm_cp<true,  true,  false>, cudaFuncAttributeMaxDynamicSharedMemorySize, GEMMC_SMEM);
        cudaFuncSetAttribute(gemm_cp<false, false, true >, cudaFuncAttributeMaxDynamicSharedMemorySize, GEMMC_SMEM);
        attr_done = true;
    }

    const int BIG = 1 << 30;
    const long EE = (long)E_DIM * E_DIM;
    const long HS = (long)H_DIM * S_DIM;   // 12288

    zero_init_k<<<1, 1024>>>();
    { dim3 g(3, 64); colmean_k<<<g, 256>>>(W_e); }
    { long nv = (long)B_DIM * S_DIM * E_DIM;
      embed_k<<<(int)((nv + 255) / 256), 256>>>(x, W_e); }
    { dim3 g(B_DIM, 16); bvec_k<<<g, E_DIM>>>(B_lr); }

    // tf32-rounded operand copies
    round_copy_k<<<4096, 256>>>((const float4*)W_e,   (float4*)p_WeR, (long)V_DIM * E_DIM / 4);
    round_copy_k<<<1024, 256>>>((const float4*)W_p,   (float4*)p_WpR, (long)1152 * E_DIM / 4);
    round_copy_k<<<1024, 256>>>((const float4*)ff_w1, (float4*)p_w1R, (long)DFF_DIM * E_DIM / 4);
    round_copy_k<<<1024, 256>>>((const float4*)ff_w2, (float4*)p_w2R, (long)E_DIM * DFF_DIM / 4);

    // transpose weights per head (rounded)
    { dim3 g(24, 24, 12), b(32, 8);
      transpose_head_k<<<g, b>>>(W_q, p_WqT);
      transpose_head_k<<<g, b>>>(W_k, p_WkT);
      transpose_head_k<<<g, b>>>(W_v, p_WvT); }

    // Q[h] = W_p(1025x768) @ WqT[h]^T        (round out)
    { dim3 g(9, 6, H_DIM);
      gemm_cp<false, true, false><<<g, 512, GEMMC_SMEM>>>(p_WpR, p_WqT, p_Q,
          Q_DIM, E_DIM, E_DIM, E_DIM, E_DIM, E_DIM,
          0L, EE, (long)Q_DIM * E_DIM, 0L, 1, BIG, 0L,
          nullptr, 1, 1.0f, nullptr, 0L); }
    // K[h] = W_p[:1024] @ WkT[h]^T           (round out)
    { dim3 g(8, 6, H_DIM);
      gemm_cp<false, true, false><<<g, 512, GEMMC_SMEM>>>(p_WpR, p_WkT, p_K,
          S_DIM, E_DIM, E_DIM, E_DIM, E_DIM, E_DIM,
          0L, EE, (long)S_DIM * E_DIM, 0L, 1, BIG, 0L,
          nullptr, 1, 1.0f, nullptr, 0L); }
    // attnT[q, h*S+s] = Q[h] @ K[h]^T        (no round; softmax rounds)
    { dim3 g(9, 8, H_DIM);
      gemm_cp<false, false, false><<<g, 512, GEMMC_SMEM>>>(p_Q, p_K, p_attnT,
          Q_DIM, S_DIM, E_DIM, E_DIM, E_DIM, (int)HS,
          (long)Q_DIM * E_DIM, (long)S_DIM * E_DIM, (long)S_DIM, 0L, 1, BIG, 0L,
          nullptr, 1, 1.0f, nullptr, 0L); }
    softmax_k<<<Q_DIM * H_DIM, 256>>>(p_attnT);

    // VtT[b][e][h*S+s] = A_lr[h] * (WvT[h] @ v[b]^T); z = h*B + b   (round out)
    { dim3 g(6, 8, H_DIM * B_DIM);
      gemm_cp<false, true, false><<<g, 512, GEMMC_SMEM>>>(p_WvT, p_v, p_VtT,
          E_DIM, S_DIM, E_DIM, E_DIM, E_DIM, (int)HS,
          EE, (long)S_DIM * E_DIM, (long)S_DIM, (long)E_DIM * HS, B_DIM, B_DIM, 0L,
          A_lr, H_DIM, 1.0f, nullptr, 0L); }
    // f[b] = attnT(1025x12288) @ VtT[b]^T / S + bvec[b]   (round out)
    { dim3 g(9, 6, B_DIM);
      gemm_cp<false, true, false><<<g, 512, GEMMC_SMEM>>>(p_attnT, p_VtT, p_f,
          Q_DIM, E_DIM, (int)HS, (int)HS, (int)HS, E_DIM,
          0L, (long)E_DIM * HS, (long)Q_DIM * E_DIM, 0L, 1, BIG, 0L,
          nullptr, 1, 1.0f / (float)S_DIM, p_bvec, (long)E_DIM); }
    // h1 = gelu(f @ ff_w1^T)                 (gelu + round out)
    { dim3 g(33, 24, 1);
      gemm_cp<true, true, false><<<g, 512, GEMMC_SMEM>>>(p_f, p_w1R, p_h1,
          B_DIM * Q_DIM, DFF_DIM, E_DIM, E_DIM, E_DIM, DFF_DIM,
          0L, 0L, 0L, 0L, 1, BIG, 0L,
          nullptr, 1, 1.0f, nullptr, 0L); }
    // f2 = h1 @ ff_w2^T                      (round out)
    { dim3 g(33, 6, 1);
      gemm_cp<false, true, false><<<g, 512, GEMMC_SMEM>>>(p_h1, p_w2R, p_f2,
          B_DIM * Q_DIM, E_DIM, DFF_DIM, DFF_DIM, DFF_DIM, E_DIM,
          0L, 0L, 0L, 0L, 1, BIG, 0L,
          nullptr, 1, 1.0f, nullptr, 0L); }
    // logits: M=4096 (batch folded via A row remap), N=50257   (no round)
    { dim3 g(32, 393, 1);
      gemm_cp<false, false, true><<<g, 512, GEMMC_SMEM>>>(p_f2, p_WeR, out,
          B_DIM * S_DIM, V_DIM, E_DIM, E_DIM, E_DIM, V_DIM,
          0L, 0L, 0L, 0L, 1, BIG, (long)Q_DIM * E_DIM,
          nullptr, 1, 1.0f, nullptr, 0L); }
}

// round 8
// speedup vs baseline: 2.0286x; 1.0315x over previous
#include <cuda_runtime.h>
#include <math.h>
#include <stdint.h>

#define E_DIM   768
#define S_DIM   1024
#define B_DIM   4
#define H_DIM   12
#define V_DIM   50257
#define DFF_DIM 3072
#define Q_DIM   1025   // S+1

// ------------------------- scratch (static device globals) -------------------------
__device__ float g_meanWe[E_DIM];
__device__ float g_v    [(long)B_DIM*S_DIM*E_DIM];
__device__ float g_bvec [B_DIM*E_DIM];
__device__ float g_WeR  [(long)V_DIM*E_DIM];                 // tf32-rounded W_e
__device__ float g_WpR  [(long)1152*E_DIM];                  // tf32-rounded W_p
__device__ float g_w1R  [(long)DFF_DIM*E_DIM];
__device__ float g_w2R  [(long)E_DIM*DFF_DIM];
__device__ float g_WqT  [(long)H_DIM*E_DIM*E_DIM];
__device__ float g_WkT  [(long)H_DIM*E_DIM*E_DIM];
__device__ float g_WvT  [(long)H_DIM*E_DIM*E_DIM];
__device__ float g_Q    [(long)H_DIM*Q_DIM*E_DIM];
__device__ float g_K    [(long)H_DIM*S_DIM*E_DIM];
__device__ float g_attnT[(long)Q_DIM*H_DIM*S_DIM];           // (q, h*S+s)
__device__ float g_VtT  [(long)B_DIM*E_DIM*H_DIM*S_DIM];     // (b, e, h*S+s)
__device__ float g_f    [(long)B_DIM*Q_DIM*E_DIM];
__device__ float g_h1   [(long)B_DIM*Q_DIM*DFF_DIM];
__device__ float g_f2   [(long)B_DIM*Q_DIM*E_DIM];

// ------------------------- helpers -------------------------
__device__ __forceinline__ uint32_t f2tf(float f) {
    uint32_t u; asm("cvt.rna.tf32.f32 %0, %1;" : "=r"(u) : "f"(f)); return u;
}
__device__ __forceinline__ float rna(float f) { return __uint_as_float(f2tf(f)); }

__device__ __forceinline__ uint32_t s2u(const void* p) {
    uint32_t a;
    asm("{ .reg .u64 t; cvta.to.shared.u64 t, %1; cvt.u32.u64 %0, t; }" : "=r"(a) : "l"(p));
    return a;
}
__device__ __forceinline__ void cpa16(uint32_t dst, const float* src, int szbytes) {
    asm volatile("cp.async.cg.shared.global [%0], [%1], 16, %2;" :: "r"(dst), "l"(src), "r"(szbytes));
}
#define CP_COMMIT()  asm volatile("cp.async.commit_group;" ::: "memory")
#define CP_WAIT(n)   asm volatile("cp.async.wait_group %0;" :: "n"(n) : "memory")

__device__ __forceinline__ void mma8(float* c, uint32_t a0, uint32_t a1, uint32_t a2, uint32_t a3,
                                     uint32_t b0, uint32_t b1) {
    asm volatile("mma.sync.aligned.m16n8k8.row.col.f32.tf32.tf32.f32 "
        "{%0,%1,%2,%3}, {%4,%5,%6,%7}, {%8,%9}, {%0,%1,%2,%3};"
        : "+f"(c[0]), "+f"(c[1]), "+f"(c[2]), "+f"(c[3])
        : "r"(a0), "r"(a1), "r"(a2), "r"(a3), "r"(b0), "r"(b1));
}

union F4 { float4 v; uint32_t u[4]; };

// ------------------------- small kernels -------------------------
__global__ void zero_init_k() {
    int t = threadIdx.x;
    if (t < E_DIM) g_meanWe[t] = 0.0f;
    for (int i = t; i < B_DIM * E_DIM; i += 1024) g_bvec[i] = 0.0f;
}

__global__ void colmean_k(const float* __restrict__ W_e) {
    int e = blockIdx.x * 256 + threadIdx.x;
    int chunk = blockIdx.y;
    const int CH = (V_DIM + 63) / 64;
    int v0 = chunk * CH;
    int v1 = v0 + CH; if (v1 > V_DIM) v1 = V_DIM;
    float s = 0.0f;
    for (int v = v0; v < v1; v++) s += W_e[(long)v * E_DIM + e];
    atomicAdd(&g_meanWe[e], s * (1.0f / 50257.0f));
}

__global__ void embed_k(const int* __restrict__ x, const float* __restrict__ W_e) {
    long i = (long)blockIdx.x * blockDim.x + threadIdx.x;
    const long n = (long)B_DIM * S_DIM * E_DIM;
    if (i >= n) return;
    int e = (int)(i % E_DIM);
    long bs = i / E_DIM;
    g_v[i] = rna(W_e[(long)x[bs] * E_DIM + e] - g_meanWe[e]);
}

__global__ void bvec_k(const float* __restrict__ Blr) {
    int b = blockIdx.x;
    int chunk = blockIdx.y;
    int e = threadIdx.x;
    const float* vb = g_v + (long)b * S_DIM * E_DIM + (long)chunk * 64 * E_DIM + e;
    float s = 0.0f;
    #pragma unroll 4
    for (int t = 0; t < 64; t++) s += vb[(long)t * E_DIM];
    atomicAdd(&g_bvec[b * E_DIM + e], s * Blr[0] * (1.0f / (float)S_DIM));
}

__global__ void round_copy_k(const float4* __restrict__ s, float4* __restrict__ d, long n4) {
    long i = (long)blockIdx.x * blockDim.x + threadIdx.x;
    long stride = (long)gridDim.x * blockDim.x;
    for (; i < n4; i += stride) {
        float4 v = s[i];
        v.x = rna(v.x); v.y = rna(v.y); v.z = rna(v.z); v.w = rna(v.w);
        d[i] = v;
    }
}

// per-head transpose with tf32 rounding: out[h][j][i] = rna(in[h][i][j])
__global__ void transpose_head_k(const float* __restrict__ in, float* __restrict__ out) {
    __shared__ float tile[32][33];
    int h = blockIdx.z;
    int i0 = blockIdx.y * 32, j0 = blockIdx.x * 32;
    const float* src = in + (long)h * E_DIM * E_DIM;
    float* dst = out + (long)h * E_DIM * E_DIM;
    int tx = threadIdx.x, ty = threadIdx.y;
    #pragma unroll
    for (int r = 0; r < 32; r += 8)
        tile[ty + r][tx] = src[(long)(i0 + ty + r) * E_DIM + j0 + tx];
    __syncthreads();
    #pragma unroll
    for (int r = 0; r < 32; r += 8)
        dst[(long)(j0 + ty + r) * E_DIM + i0 + tx] = rna(tile[tx][ty + r]);
}

__global__ void softmax_k(float* __restrict__ attnT) {
    int q = blockIdx.x / H_DIM;
    int h = blockIdx.x % H_DIM;
    float* row = attnT + (long)q * (H_DIM * S_DIM) + (long)h * S_DIM;
    int tid = threadIdx.x;
    const float scale = 0.03608439182435161f;   // 1/sqrt(768)
    float4 v = reinterpret_cast<float4*>(row)[tid];
    float m = fmaxf(fmaxf(v.x, v.y), fmaxf(v.z, v.w));
    __shared__ float red[8];
    #pragma unroll
    for (int o = 16; o > 0; o >>= 1) m = fmaxf(m, __shfl_xor_sync(0xffffffffu, m, o));
    if ((tid & 31) == 0) red[tid >> 5] = m;
    __syncthreads();
    m = red[0];
    #pragma unroll
    for (int w = 1; w < 8; w++) m = fmaxf(m, red[w]);
    float ex = expf(scale * (v.x - m));
    float ey = expf(scale * (v.y - m));
    float ez = expf(scale * (v.z - m));
    float ew = expf(scale * (v.w - m));
    float s = ex + ey + ez + ew;
    #pragma unroll
    for (int o = 16; o > 0; o >>= 1) s += __shfl_xor_sync(0xffffffffu, s, o);
    __syncthreads();
    if ((tid & 31) == 0) red[tid >> 5] = s;
    __syncthreads();
    s = 0.0f;
    #pragma unroll
    for (int w = 0; w < 8; w++) s += red[w];
    float inv = 1.0f / s;
    v.x = rna(ex * inv); v.y = rna(ey * inv); v.z = rna(ez * inv); v.w = rna(ew * inv);
    reinterpret_cast<float4*>(row)[tid] = v;
}

// ------------------------- cp.async tf32 NT GEMM (LDS.128 fragments) -------------------------
// C[m,n] = alpha * sum_k A[m,k] * B[n,k] (+ bias[n]) [+ GELU] [+ tf32 round]
// Tile 128x128x32, 512 threads, 16 warps (4x4), warp tile 32x32.
// k-permutation: mma k-slot (ks, t)   <-> logical k = 4t+ks      (chunk kc = t)
//                mma k-slot (ks, t+4) <-> logical k = 16+4t+ks   (chunk kc = t+4)
// smem: row r (128B = 8 chunks of 16B); chunk kc stored at physical chunk
//       2*(kc&3) + ((kc>>2) ^ (r&1))
// -> producer STS conflict-free; consumer loads 2 LDS.128 per row, conflict-free.

#define NS 4
#define STAGE_FLOATS 8192           // 32KB: A 128x32 | B 128x32
#define GEMMC_SMEM (NS * STAGE_FLOATS * 4)

template<bool GELU, bool ROUND, bool ABATCH>
__global__ __launch_bounds__(512, 1)
void gemm_cp(const float* __restrict__ Ag, const float* __restrict__ Bg,
             float* __restrict__ Cg,
             int M, int N, int K, int lda, int ldb, int ldc,
             long sA, long sB, long sC1, long sC2, int divA, int modB, long abStride,
             const float* __restrict__ alphaPtr, int alphaMod, float alphaScale,
             const float* __restrict__ biasPtr, long biasStride)
{
    extern __shared__ float sm[];    // NS stages: [A 4096][B 4096]

    int z = blockIdx.z;
    const float* A = Ag + (long)(z / divA) * sA;
    const float* B = Bg + (long)(z % modB) * sB;
    float* C = Cg + (long)(z / divA) * sC1 + (long)(z % modB) * sC2;
    float alpha = alphaScale;
    if (alphaPtr) alpha *= alphaPtr[(z / divA) % alphaMod];
    const float* bias = biasPtr ? (biasPtr + (long)z * biasStride) : nullptr;

    int bm = blockIdx.x * 128;
    int bn = blockIdx.y * 128;
    int tid = threadIdx.x;
    int warp = tid >> 5, lane = tid & 31;
    int wm = warp >> 2, wn = warp & 3;     // 4x4 warp grid
    int g = lane >> 2, t = lane & 3;
    int pr = g & 1;                        // row-parity of every row this thread touches
    int cLo = 2 * t + pr;                  // physical chunk of logical chunk kc=t
    int cHi = 2 * t + 1 - pr;              // physical chunk of logical chunk kc=t+4

    // producer mapping: row = tid>>2 (0..127), logical chunks lc and lc+4
    int lrow = tid >> 2;
    int lc = tid & 3;
    int rp = lrow & 1;
    int am = bm + lrow;
    bool aok = am < M;
    const float* abase;
    if (ABATCH) abase = aok ? (A + (long)(am >> 10) * abStride + (long)(am & 1023) * lda) : A;
    else        abase = aok ? (A + (long)am * lda) : A;
    int nn = bn + lrow;
    bool bok = nn < N;
    const float* bbase = bok ? (B + (long)nn * ldb) : B;
    int asz = aok ? 16 : 0, bsz = bok ? 16 : 0;

    uint32_t smb = s2u(sm);
    uint32_t dA0 = smb + lrow * 128 + ((2 * lc + rp)     << 4);   // kc = lc
    uint32_t dA1 = smb + lrow * 128 + ((2 * lc + 1 - rp) << 4);   // kc = lc+4
    uint32_t dB0 = dA0 + 16384;
    uint32_t dB1 = dA1 + 16384;

    float acc[2][4][4];
    #pragma unroll
    for (int i = 0; i < 2; i++)
        #pragma unroll
        for (int j = 0; j < 4; j++)
            #pragma unroll
            for (int r = 0; r < 4; r++) acc[i][j][r] = 0.0f;

    int nt = K >> 5;

    // prologue: tiles 0 .. NS-2
    #pragma unroll
    for (int p = 0; p < NS - 1; p++) {
        uint32_t off = p * (STAGE_FLOATS * 4);
        int k0 = p * 32;
        cpa16(dA0 + off, abase + k0 + lc * 4,      asz);
        cpa16(dA1 + off, abase + k0 + lc * 4 + 16, asz);
        cpa16(dB0 + off, bbase + k0 + lc * 4,      bsz);
        cpa16(dB1 + off, bbase + k0 + lc * 4 + 16, bsz);
        CP_COMMIT();
    }

    for (int it = 0; it < nt; it++) {
        int s = it & (NS - 1);
        CP_WAIT(NS - 2);
        __syncthreads();

        int T = it + NS - 1;
        if (T < nt) {
            uint32_t off = (T & (NS - 1)) * (STAGE_FLOATS * 4);
            int k0 = T << 5;
            cpa16(dA0 + off, abase + k0 + lc * 4,      asz);
            cpa16(dA1 + off, abase + k0 + lc * 4 + 16, asz);
            cpa16(dB0 + off, bbase + k0 + lc * 4,      bsz);
            cpa16(dB1 + off, bbase + k0 + lc * 4 + 16, bsz);
        }
        CP_COMMIT();

        const float* As = sm + s * STAGE_FLOATS;
        const float* Bs = As + 4096;

        // fragment loads: 16 x LDS.128 covering the whole 32-deep K tile
        F4 alo[2][2], ahi[2][2], blo[4], bhi[4];
        #pragma unroll
        for (int i = 0; i < 2; i++) {
            int r0 = wm * 32 + i * 16 + g;
            const float4* p0 = reinterpret_cast<const float4*>(As + r0 * 32);
            const float4* p1 = reinterpret_cast<const float4*>(As + (r0 + 8) * 32);
            alo[i][0].v = p0[cLo]; ahi[i][0].v = p0[cHi];
            alo[i][1].v = p1[cLo]; ahi[i][1].v = p1[cHi];
        }
        #pragma unroll
        for (int j = 0; j < 4; j++) {
            int c0 = wn * 32 + j * 8 + g;
            const float4* p = reinterpret_cast<const float4*>(Bs + c0 * 32);
            blo[j].v = p[cLo]; bhi[j].v = p[cHi];
        }

        #pragma unroll
        for (int ks = 0; ks < 4; ks++) {
            #pragma unroll
            for (int i = 0; i < 2; i++)
                #pragma unroll
                for (int j = 0; j < 4; j++)
                    mma8(acc[i][j],
                         alo[i][0].u[ks], alo[i][1].u[ks],
                         ahi[i][0].u[ks], ahi[i][1].u[ks],
                         blo[j].u[ks],    bhi[j].u[ks]);
        }
        __syncthreads();
    }

    // ---- epilogue (scalar stores; ldc may be odd) ----
    #pragma unroll
    for (int i = 0; i < 2; i++) {
        #pragma unroll
        for (int j = 0; j < 4; j++) {
            int n0 = bn + wn * 32 + j * 8 + 2 * t;
            #pragma unroll
            for (int half = 0; half < 2; half++) {
                int m = bm + wm * 32 + i * 16 + g + half * 8;
                if (m >= M) continue;
                float v0 = acc[i][j][half * 2 + 0] * alpha;
                float v1 = acc[i][j][half * 2 + 1] * alpha;
                if (bias) { v0 += bias[n0]; if (n0 + 1 < N) v1 += bias[n0 + 1]; }
                if (GELU) {
                    v0 = 0.5f * v0 * (1.0f + erff(v0 * 0.70710678118654752f));
                    v1 = 0.5f * v1 * (1.0f + erff(v1 * 0.70710678118654752f));
                }
                if (ROUND) { v0 = rna(v0); v1 = rna(v1); }
                float* crow = C + (long)m * ldc;
                if (n0 < N)     crow[n0]     = v0;
                if (n0 + 1 < N) crow[n0 + 1] = v1;
            }
        }
    }
}

// ------------------------- launch -------------------------
extern "C" void kernel_launch(void* const* d_in, const int* in_sizes, int n_in,
                              void* d_out, int out_size) {
    (void)in_sizes; (void)n_in; (void)out_size;
    const int*   x     = (const int*)  d_in[0];
    const float* W_e   = (const float*)d_in[1];
    const float* W_p   = (const float*)d_in[2];
    const float* W_q   = (const float*)d_in[3];
    const float* W_k   = (const float*)d_in[4];
    const float* W_v   = (const float*)d_in[5];
    const float* A_lr  = (const float*)d_in[6];
    const float* B_lr  = (const float*)d_in[7];
    const float* ff_w1 = (const float*)d_in[8];
    const float* ff_w2 = (const float*)d_in[9];
    float* out = (float*)d_out;

    float *p_v, *p_bvec, *p_WeR, *p_WpR, *p_w1R, *p_w2R;
    float *p_WqT, *p_WkT, *p_WvT, *p_Q, *p_K, *p_attnT, *p_VtT, *p_f, *p_h1, *p_f2;
    cudaGetSymbolAddress((void**)&p_v,     g_v);
    cudaGetSymbolAddress((void**)&p_bvec,  g_bvec);
    cudaGetSymbolAddress((void**)&p_WeR,   g_WeR);
    cudaGetSymbolAddress((void**)&p_WpR,   g_WpR);
    cudaGetSymbolAddress((void**)&p_w1R,   g_w1R);
    cudaGetSymbolAddress((void**)&p_w2R,   g_w2R);
    cudaGetSymbolAddress((void**)&p_WqT,   g_WqT);
    cudaGetSymbolAddress((void**)&p_WkT,   g_WkT);
    cudaGetSymbolAddress((void**)&p_WvT,   g_WvT);
    cudaGetSymbolAddress((void**)&p_Q,     g_Q);
    cudaGetSymbolAddress((void**)&p_K,     g_K);
    cudaGetSymbolAddress((void**)&p_attnT, g_attnT);
    cudaGetSymbolAddress((void**)&p_VtT,   g_VtT);
    cudaGetSymbolAddress((void**)&p_f,     g_f);
    cudaGetSymbolAddress((void**)&p_h1,    g_h1);
    cudaGetSymbolAddress((void**)&p_f2,    g_f2);

    static bool attr_done = false;
    if (!attr_done) {
        cudaFuncSetAttribute(gemm_cp<false, true,  false>, cudaFuncAttributeMaxDynamicSharedMemorySize, GEMMC_SMEM);
        cudaFuncSetAttribute(gemm_cp<false, false, false>, cudaFuncAttributeMaxDynamicSharedMemorySize, GEMMC_SMEM);
        cudaFuncSetAttribute(gemm_cp<true,  true,  false>, cudaFuncAttributeMaxDynamicSharedMemorySize, GEMMC_SMEM);
        cudaFuncSetAttribute(gemm_cp<false, false, true >, cudaFuncAttributeMaxDynamicSharedMemorySize, GEMMC_SMEM);
        attr_done = true;
    }

    const int BIG = 1 << 30;
    const long EE = (long)E_DIM * E_DIM;
    const long HS = (long)H_DIM * S_DIM;   // 12288

    zero_init_k<<<1, 1024>>>();
    { dim3 g(3, 64); colmean_k<<<g, 256>>>(W_e); }
    { long nv = (long)B_DIM * S_DIM * E_DIM;
      embed_k<<<(int)((nv + 255) / 256), 256>>>(x, W_e); }
    { dim3 g(B_DIM, 16); bvec_k<<<g, E_DIM>>>(B_lr); }

    // tf32-rounded operand copies
    round_copy_k<<<4096, 256>>>((const float4*)W_e,   (float4*)p_WeR, (long)V_DIM * E_DIM / 4);
    round_copy_k<<<1024, 256>>>((const float4*)W_p,   (float4*)p_WpR, (long)1152 * E_DIM / 4);
    round_copy_k<<<1024, 256>>>((const float4*)ff_w1, (float4*)p_w1R, (long)DFF_DIM * E_DIM / 4);
    round_copy_k<<<1024, 256>>>((const float4*)ff_w2, (float4*)p_w2R, (long)E_DIM * DFF_DIM / 4);

    // transpose weights per head (rounded)
    { dim3 g(24, 24, 12), b(32, 8);
      transpose_head_k<<<g, b>>>(W_q, p_WqT);
      transpose_head_k<<<g, b>>>(W_k, p_WkT);
      transpose_head_k<<<g, b>>>(W_v, p_WvT); }

    // Q[h] = W_p(1025x768) @ WqT[h]^T        (round out)
    { dim3 g(9, 6, H_DIM);
      gemm_cp<false, true, false><<<g, 512, GEMMC_SMEM>>>(p_WpR, p_WqT, p_Q,
          Q_DIM, E_DIM, E_DIM, E_DIM, E_DIM, E_DIM,
          0L, EE, (long)Q_DIM * E_DIM, 0L, 1, BIG, 0L,
          nullptr, 1, 1.0f, nullptr, 0L); }
    // K[h] = W_p[:1024] @ WkT[h]^T           (round out)
    { dim3 g(8, 6, H_DIM);
      gemm_cp<false, true, false><<<g, 512, GEMMC_SMEM>>>(p_WpR, p_WkT, p_K,
          S_DIM, E_DIM, E_DIM, E_DIM, E_DIM, E_DIM,
          0L, EE, (long)S_DIM * E_DIM, 0L, 1, BIG, 0L,
          nullptr, 1, 1.0f, nullptr, 0L); }
    // attnT[q, h*S+s] = Q[h] @ K[h]^T        (no round; softmax rounds)
    { dim3 g(9, 8, H_DIM);
      gemm_cp<false, false, false><<<g, 512, GEMMC_SMEM>>>(p_Q, p_K, p_attnT,
          Q_DIM, S_DIM, E_DIM, E_DIM, E_DIM, (int)HS,
          (long)Q_DIM * E_DIM, (long)S_DIM * E_DIM, (long)S_DIM, 0L, 1, BIG, 0L,
          nullptr, 1, 1.0f, nullptr, 0L); }
    softmax_k<<<Q_DIM * H_DIM, 256>>>(p_attnT);

    // VtT[b][e][h*S+s] = A_lr[h] * (WvT[h] @ v[b]^T); z = h*B + b   (round out)
    { dim3 g(6, 8, H_DIM * B_DIM);
      gemm_cp<false, true, false><<<g, 512, GEMMC_SMEM>>>(p_WvT, p_v, p_VtT,
          E_DIM, S_DIM, E_DIM, E_DIM, E_DIM, (int)HS,
          EE, (long)S_DIM * E_DIM, (long)S_DIM, (long)E_DIM * HS, B_DIM, B_DIM, 0L,
          A_lr, H_DIM, 1.0f, nullptr, 0L); }
    // f[b] = attnT(1025x12288) @ VtT[b]^T / S + bvec[b]   (round out)
    { dim3 g(9, 6, B_DIM);
      gemm_cp<false, true, false><<<g, 512, GEMMC_SMEM>>>(p_attnT, p_VtT, p_f,
          Q_DIM, E_DIM, (int)HS, (int)HS, (int)HS, E_DIM,
          0L, (long)E_DIM * HS, (long)Q_DIM * E_DIM, 0L, 1, BIG, 0L,
          nullptr, 1, 1.0f / (float)S_DIM, p_bvec, (long)E_DIM); }
    // h1 = gelu(f @ ff_w1^T)                 (gelu + round out)
    { dim3 g(33, 24, 1);
      gemm_cp<true, true, false><<<g, 512, GEMMC_SMEM>>>(p_f, p_w1R, p_h1,
          B_DIM * Q_DIM, DFF_DIM, E_DIM, E_DIM, E_DIM, DFF_DIM,
          0L, 0L, 0L, 0L, 1, BIG, 0L,
          nullptr, 1, 1.0f, nullptr, 0L); }
    // f2 = h1 @ ff_w2^T                      (round out)
    { dim3 g(33, 6, 1);
      gemm_cp<false, true, false><<<g, 512, GEMMC_SMEM>>>(p_h1, p_w2R, p_f2,
          B_DIM * Q_DIM, E_DIM, DFF_DIM, DFF_DIM, DFF_DIM, E_DIM,
          0L, 0L, 0L, 0L, 1, BIG, 0L,
          nullptr, 1, 1.0f, nullptr, 0L); }
    // logits: M=4096 (batch folded via A row remap), N=50257   (no round)
    { dim3 g(32, 393, 1);
      gemm_cp<false, false, true><<<g, 512, GEMMC_SMEM>>>(p_f2, p_WeR, out,
          B_DIM * S_DIM, V_DIM, E_DIM, E_DIM, E_DIM, V_DIM,
          0L, 0L, 0L, 0L, 1, BIG, (long)Q_DIM * E_DIM,
          nullptr, 1, 1.0f, nullptr, 0L); }
}

// round 9
// speedup vs baseline: 4.8621x; 2.3968x over previous
#include <cuda_runtime.h>
#include <cuda_fp16.h>
#include <math.h>
#include <stdint.h>

#define E_DIM   768
#define S_DIM   1024
#define B_DIM   4
#define H_DIM   12
#define V_DIM   50257
#define DFF_DIM 3072
#define Q_DIM   1025   // S+1
#define HS_DIM  (H_DIM*S_DIM)

// ------------------------- scratch (static device globals) -------------------------
__device__ float  g_meanWe[E_DIM];
__device__ float  g_bvec [B_DIM*E_DIM];
__device__ __half g_v    [(long)B_DIM*S_DIM*E_DIM];
__device__ __half g_WeH  [(long)V_DIM*E_DIM];
__device__ __half g_WpH  [(long)Q_DIM*E_DIM];
__device__ __half g_w1H  [(long)DFF_DIM*E_DIM];
__device__ __half g_w2H  [(long)E_DIM*DFF_DIM];
__device__ __half g_WqT  [(long)H_DIM*E_DIM*E_DIM];
__device__ __half g_WkT  [(long)H_DIM*E_DIM*E_DIM];
__device__ __half g_WvT  [(long)H_DIM*E_DIM*E_DIM];
__device__ __half g_Q    [(long)H_DIM*Q_DIM*E_DIM];
__device__ __half g_K    [(long)H_DIM*S_DIM*E_DIM];
__device__ __half g_attnT[(long)Q_DIM*HS_DIM];
__device__ __half g_VtT  [(long)B_DIM*E_DIM*HS_DIM];
__device__ __half g_f    [(long)B_DIM*Q_DIM*E_DIM];
__device__ __half g_h1   [(long)B_DIM*Q_DIM*DFF_DIM];
__device__ __half g_f2   [(long)B_DIM*Q_DIM*E_DIM];

// ------------------------- helpers -------------------------
// K-permutation within 32-blocks: stored position p holds logical k = PIT(p);
// logical k is stored at position STAB(k). PIT = STAB^{-1}.
__device__ __forceinline__ int PIT(int p)  { return 2*(p>>3) + (p&1) + ((p>>1)&3)*8; }
__device__ __forceinline__ int STAB(int k) { return 8*((k&7)>>1) + (k&1) + (((k>>3)&1)<<1) + (((k>>4)&1)<<2); }

__device__ __forceinline__ uint32_t s2u(const void* p) {
    uint32_t a;
    asm("{ .reg .u64 t; cvta.to.shared.u64 t, %1; cvt.u32.u64 %0, t; }" : "=r"(a) : "l"(p));
    return a;
}
__device__ __forceinline__ void cpa16(uint32_t dst, const void* src, int szbytes) {
    asm volatile("cp.async.cg.shared.global [%0], [%1], 16, %2;" :: "r"(dst), "l"(src), "r"(szbytes));
}
#define CP_COMMIT()  asm volatile("cp.async.commit_group;" ::: "memory")
#define CP_WAIT(n)   asm volatile("cp.async.wait_group %0;" :: "n"(n) : "memory")

__device__ __forceinline__ void mma16(float* c, uint32_t a0, uint32_t a1, uint32_t a2, uint32_t a3,
                                      uint32_t b0, uint32_t b1) {
    asm volatile("mma.sync.aligned.m16n8k16.row.col.f32.f16.f16.f32 "
        "{%0,%1,%2,%3}, {%4,%5,%6,%7}, {%8,%9}, {%0,%1,%2,%3};"
        : "+f"(c[0]), "+f"(c[1]), "+f"(c[2]), "+f"(c[3])
        : "r"(a0), "r"(a1), "r"(a2), "r"(a3), "r"(b0), "r"(b1));
}

union F4 { float4 v; uint32_t u[4]; };

__device__ __forceinline__ void stv(float* p, float v)  { *p = v; }
__device__ __forceinline__ void stv(__half* p, float v) { *p = __float2half(v); }

// ------------------------- small kernels -------------------------
__global__ void zero_init_k() {
    int t = threadIdx.x;
    if (t < E_DIM) g_meanWe[t] = 0.0f;
    for (int i = t; i < B_DIM * E_DIM; i += 1024) g_bvec[i] = 0.0f;
}

__global__ void colmean_k(const float* __restrict__ W_e) {
    int e = blockIdx.x * 256 + threadIdx.x;
    int chunk = blockIdx.y;
    const int CH = (V_DIM + 63) / 64;
    int v0 = chunk * CH;
    int v1 = v0 + CH; if (v1 > V_DIM) v1 = V_DIM;
    float s = 0.0f;
    for (int v = v0; v < v1; v++) s += W_e[(long)v * E_DIM + e];
    atomicAdd(&g_meanWe[e], s * (1.0f / 50257.0f));
}

// fp16 convert with K-permutation: dst[i] = half(src[(i&~31) + PIT(i&31)])
// valid because every row length is a multiple of 32.
__global__ void convert_perm_k(const float* __restrict__ s, __half* __restrict__ d, long n) {
    long i = (long)blockIdx.x * blockDim.x + threadIdx.x;
    long stride = (long)gridDim.x * blockDim.x;
    for (; i < n; i += stride) {
        long blk = i & ~31L;
        d[i] = __float2half(s[blk + PIT((int)(i & 31))]);
    }
}

// v[bs][p] = half(W_e[x[bs]][e_log] - mean[e_log]), e_log = perm(p)
__global__ void embed_k(const int* __restrict__ x, const float* __restrict__ W_e) {
    long i = (long)blockIdx.x * blockDim.x + threadIdx.x;
    const long n = (long)B_DIM * S_DIM * E_DIM;
    if (i >= n) return;
    int p = (int)(i % E_DIM);
    long bs = i / E_DIM;
    int e = (p & ~31) + PIT(p & 31);
    g_v[i] = __float2half(W_e[(long)x[bs] * E_DIM + e] - g_meanWe[e]);
}

// bvec[b][e_log] = B_lr * sum_s v[b,s,p] / S  (v stored permuted)
__global__ void bvec_k(const float* __restrict__ Blr) {
    int b = blockIdx.x;
    int chunk = blockIdx.y;
    int p = threadIdx.x;
    const __half* vb = g_v + (long)b * S_DIM * E_DIM + (long)chunk * 64 * E_DIM + p;
    float s = 0.0f;
    #pragma unroll 4
    for (int t = 0; t < 64; t++) s += __half2float(vb[(long)t * E_DIM]);
    int e = (p & ~31) + PIT(p & 31);
    atomicAdd(&g_bvec[b * E_DIM + e], s * Blr[0] * (1.0f / (float)S_DIM));
}

// per-head transpose fp32->fp16: out[h][j][i_perm] with K-dim (i) permuted
__global__ void transpose_head_k(const float* __restrict__ in, __half* __restrict__ out) {
    __shared__ float tile[32][33];
    int h = blockIdx.z;
    int i0 = blockIdx.y * 32, j0 = blockIdx.x * 32;
    const float* src = in + (long)h * E_DIM * E_DIM;
    __half* dst = out + (long)h * E_DIM * E_DIM;
    int tx = threadIdx.x, ty = threadIdx.y;
    #pragma unroll
    for (int r = 0; r < 32; r += 8)
        tile[ty + r][tx] = src[(long)(i0 + ty + r) * E_DIM + j0 + tx];
    __syncthreads();
    #pragma unroll
    for (int r = 0; r < 32; r += 8)
        dst[(long)(j0 + ty + r) * E_DIM + i0 + tx] = __float2half(tile[PIT(tx)][ty + r]);
}

// softmax over 1024-chunks of half attnT (permutation-invariant)
__global__ void softmax_h(__half* __restrict__ attnT) {
    int q = blockIdx.x / H_DIM;
    int h = blockIdx.x % H_DIM;
    __half2* row = reinterpret_cast<__half2*>(attnT + (long)q * HS_DIM + (long)h * S_DIM);
    int tid = threadIdx.x;   // 256
    const float scale = 0.03608439182435161f;   // 1/sqrt(768)
    __half2 h0 = row[2 * tid], h1v = row[2 * tid + 1];
    float2 f0 = __half22float2(h0), f1 = __half22float2(h1v);
    float m = fmaxf(fmaxf(f0.x, f0.y), fmaxf(f1.x, f1.y));
    __shared__ float red[8];
    #pragma unroll
    for (int o = 16; o > 0; o >>= 1) m = fmaxf(m, __shfl_xor_sync(0xffffffffu, m, o));
    if ((tid & 31) == 0) red[tid >> 5] = m;
    __syncthreads();
    m = red[0];
    #pragma unroll
    for (int w = 1; w < 8; w++) m = fmaxf(m, red[w]);
    float e0 = expf(scale * (f0.x - m));
    float e1 = expf(scale * (f0.y - m));
    float e2 = expf(scale * (f1.x - m));
    float e3 = expf(scale * (f1.y - m));
    float s = e0 + e1 + e2 + e3;
    #pragma unroll
    for (int o = 16; o > 0; o >>= 1) s += __shfl_xor_sync(0xffffffffu, s, o);
    __syncthreads();
    if ((tid & 31) == 0) red[tid >> 5] = s;
    __syncthreads();
    s = 0.0f;
    #pragma unroll
    for (int w = 0; w < 8; w++) s += red[w];
    float inv = 1.0f / s;
    row[2 * tid]     = __floats2half2_rn(e0 * inv, e1 * inv);
    row[2 * tid + 1] = __floats2half2_rn(e2 * inv, e3 * inv);
}

// ------------------------- fp16 cp.async NT GEMM -------------------------
// C[m,n] = ((alpha * sum_k A[m,k]*B[n,k]) + bias[n]) [GELU] * storeScale
// All operands fp16, K-permuted in gmem. Tile 128x128x64(halfs).
// 512 threads, 16 warps (4x4), warp tile 32x32, mma.m16n8k16.
// smem row = 64 halfs (128B) = 8 chunks; logical chunk c at c ^ ((row&1)*4).
// PERM: output cols stored sigma-permuted (consumed as K later).

#define NS 4
#define STAGE_HALFS 16384           // 32KB: A 128x64 | B 128x64
#define GEMMH_SMEM (NS * STAGE_HALFS * 2)

template<bool GELU, bool ABATCH, bool PERM, typename OutT>
__global__ __launch_bounds__(512, 1)
void gemm_h(const __half* __restrict__ Ag, const __half* __restrict__ Bg,
            OutT* __restrict__ Cg,
            int M, int N, int K, int lda, int ldb, int ldc,
            long sA, long sB, long sC1, long sC2, int divA, int modB, long abStride,
            const float* __restrict__ alphaPtr, int alphaMod, float alphaScale,
            const float* __restrict__ biasPtr, long biasStride, float storeScale)
{
    extern __shared__ __half smh[];

    int z = blockIdx.z;
    const __half* A = Ag + (long)(z / divA) * sA;
    const __half* B = Bg + (long)(z % modB) * sB;
    OutT* C = Cg + (long)(z / divA) * sC1 + (long)(z % modB) * sC2;
    float alpha = alphaScale;
    if (alphaPtr) alpha *= alphaPtr[(z / divA) % alphaMod];
    const float* bias = biasPtr ? (biasPtr + (long)z * biasStride) : nullptr;

    int bm = blockIdx.x * 128;
    int bn = blockIdx.y * 128;
    int tid = threadIdx.x;
    int warp = tid >> 5, lane = tid & 31;
    int wm = warp >> 2, wn = warp & 3;     // 4x4 warp grid
    int g = lane >> 2, t = lane & 3;
    int gx = (g & 1) << 2;                 // row-parity XOR for this thread's rows/cols

    // producer: row = tid>>2 (0..127), logical chunks lc and lc+4 of the 8-chunk row
    int lrow = tid >> 2;
    int lc = tid & 3;
    int rpx = (lrow & 1) << 2;
    int am = bm + lrow;
    bool aok = am < M;
    const __half* abase;
    if (ABATCH) abase = aok ? (A + (long)(am >> 10) * abStride + (long)(am & 1023) * lda) : A;
    else        abase = aok ? (A + (long)am * lda) : A;
    int nn = bn + lrow;
    bool bok = nn < N;
    const __half* bbase = bok ? (B + (long)nn * ldb) : B;
    int asz = aok ? 16 : 0, bsz = bok ? 16 : 0;

    uint32_t smb = s2u(smh);
    uint32_t dA0 = smb + (uint32_t)(lrow * 128 + ((lc      ^ rpx) << 4));
    uint32_t dA1 = smb + (uint32_t)(lrow * 128 + (((lc + 4) ^ rpx) << 4));
    uint32_t dB0 = dA0 + STAGE_HALFS;      // bytes: 16384 = B half of stage
    uint32_t dB1 = dA1 + STAGE_HALFS;

    float acc[2][4][4];
    #pragma unroll
    for (int i = 0; i < 2; i++)
        #pragma unroll
        for (int j = 0; j < 4; j++)
            #pragma unroll
            for (int r = 0; r < 4; r++) acc[i][j][r] = 0.0f;

    int nt = K >> 6;     // K multiple of 64

    #pragma unroll
    for (int p = 0; p < NS - 1; p++) {
        uint32_t off = p * (STAGE_HALFS * 2);
        int k0 = p * 64;
        cpa16(dA0 + off, abase + k0 + lc * 8,        asz);
        cpa16(dA1 + off, abase + k0 + (lc + 4) * 8,  asz);
        cpa16(dB0 + off, bbase + k0 + lc * 8,        bsz);
        cpa16(dB1 + off, bbase + k0 + (lc + 4) * 8,  bsz);
        CP_COMMIT();
    }

    for (int it = 0; it < nt; it++) {
        int s = it & (NS - 1);
        CP_WAIT(NS - 2);
        __syncthreads();

        int T = it + NS - 1;
        if (T < nt) {
            uint32_t off = (T & (NS - 1)) * (STAGE_HALFS * 2);
            int k0 = T << 6;
            cpa16(dA0 + off, abase + k0 + lc * 8,        asz);
            cpa16(dA1 + off, abase + k0 + (lc + 4) * 8,  asz);
            cpa16(dB0 + off, bbase + k0 + lc * 8,        bsz);
            cpa16(dB1 + off, bbase + k0 + (lc + 4) * 8,  bsz);
        }
        CP_COMMIT();

        const __half* As = smh + s * STAGE_HALFS;
        const __half* Bs = As + 8192;

        #pragma unroll
        for (int h = 0; h < 2; h++) {
            int cx = (t + 4 * h) ^ gx;     // stored chunk index for this thread
            F4 a[2][2], b[4];
            #pragma unroll
            for (int i = 0; i < 2; i++) {
                int r0 = wm * 32 + i * 16 + g;
                a[i][0].v = *reinterpret_cast<const float4*>(As + r0 * 64 + cx * 8);
                a[i][1].v = *reinterpret_cast<const float4*>(As + (r0 + 8) * 64 + cx * 8);
            }
            #pragma unroll
            for (int j = 0; j < 4; j++) {
                int cb = wn * 32 + j * 8 + g;
                b[j].v = *reinterpret_cast<const float4*>(Bs + cb * 64 + cx * 8);
            }
            #pragma unroll
            for (int i = 0; i < 2; i++)
                #pragma unroll
                for (int j = 0; j < 4; j++) {
                    mma16(acc[i][j], a[i][0].u[0], a[i][1].u[0], a[i][0].u[1], a[i][1].u[1],
                          b[j].u[0], b[j].u[1]);
                    mma16(acc[i][j], a[i][0].u[2], a[i][1].u[2], a[i][0].u[3], a[i][1].u[3],
                          b[j].u[2], b[j].u[3]);
                }
        }
        __syncthreads();
    }

    // ---- epilogue ----
    #pragma unroll
    for (int i = 0; i < 2; i++) {
        #pragma unroll
        for (int j = 0; j < 4; j++) {
            int nl = wn * 32 + j * 8 + 2 * t;               // logical col in tile
            int n0 = bn + nl;                               // logical global col
            int sn = PERM ? (bn + (nl & ~31) + STAB(nl & 31)) : n0;
            #pragma unroll
            for (int half = 0; half < 2; half++) {
                int m = bm + wm * 32 + i * 16 + g + half * 8;
                if (m >= M) continue;
                float v0 = acc[i][j][half * 2 + 0] * alpha;
                float v1 = acc[i][j][half * 2 + 1] * alpha;
                if (bias) { v0 += bias[n0]; if (n0 + 1 < N) v1 += bias[n0 + 1]; }
                if (GELU) {
                    v0 = 0.5f * v0 * (1.0f + erff(v0 * 0.70710678118654752f));
                    v1 = 0.5f * v1 * (1.0f + erff(v1 * 0.70710678118654752f));
                }
                v0 *= storeScale; v1 *= storeScale;
                OutT* crow = C + (long)m * ldc;
                if (n0 < N)     stv(crow + sn,     v0);
                if (n0 + 1 < N) stv(crow + sn + 1, v1);
            }
        }
    }
}

// ------------------------- launch -------------------------
extern "C" void kernel_launch(void* const* d_in, const int* in_sizes, int n_in,
                              void* d_out, int out_size) {
    (void)in_sizes; (void)n_in; (void)out_size;
    const int*   x     = (const int*)  d_in[0];
    const float* W_e   = (const float*)d_in[1];
    const float* W_p   = (const float*)d_in[2];
    const float* W_q   = (const float*)d_in[3];
    const float* W_k   = (const float*)d_in[4];
    const float* W_v   = (const float*)d_in[5];
    const float* A_lr  = (const float*)d_in[6];
    const float* B_lr  = (const float*)d_in[7];
    const float* ff_w1 = (const float*)d_in[8];
    const float* ff_w2 = (const float*)d_in[9];
    float* out = (float*)d_out;

    float *p_bvec;
    __half *p_v, *p_WeH, *p_WpH, *p_w1H, *p_w2H;
    __half *p_WqT, *p_WkT, *p_WvT, *p_Q, *p_K, *p_attnT, *p_VtT, *p_f, *p_h1, *p_f2;
    cudaGetSymbolAddress((void**)&p_bvec,  g_bvec);
    cudaGetSymbolAddress((void**)&p_v,     g_v);
    cudaGetSymbolAddress((void**)&p_WeH,   g_WeH);
    cudaGetSymbolAddress((void**)&p_WpH,   g_WpH);
    cudaGetSymbolAddress((void**)&p_w1H,   g_w1H);
    cudaGetSymbolAddress((void**)&p_w2H,   g_w2H);
    cudaGetSymbolAddress((void**)&p_WqT,   g_WqT);
    cudaGetSymbolAddress((void**)&p_WkT,   g_WkT);
    cudaGetSymbolAddress((void**)&p_WvT,   g_WvT);
    cudaGetSymbolAddress((void**)&p_Q,     g_Q);
    cudaGetSymbolAddress((void**)&p_K,     g_K);
    cudaGetSymbolAddress((void**)&p_attnT, g_attnT);
    cudaGetSymbolAddress((void**)&p_VtT,   g_VtT);
    cudaGetSymbolAddress((void**)&p_f,     g_f);
    cudaGetSymbolAddress((void**)&p_h1,    g_h1);
    cudaGetSymbolAddress((void**)&p_f2,    g_f2);

    static bool attr_done = false;
    if (!attr_done) {
        cudaFuncSetAttribute(gemm_h<false, false, true,  __half>, cudaFuncAttributeMaxDynamicSharedMemorySize, GEMMH_SMEM);
        cudaFuncSetAttribute(gemm_h<true,  false, true,  __half>, cudaFuncAttributeMaxDynamicSharedMemorySize, GEMMH_SMEM);
        cudaFuncSetAttribute(gemm_h<false, true,  false, float >, cudaFuncAttributeMaxDynamicSharedMemorySize, GEMMH_SMEM);
        attr_done = true;
    }

    const int BIG = 1 << 30;
    const long EE = (long)E_DIM * E_DIM;
    const long HS = (long)HS_DIM;
    const float SS = 1024.0f, ISS = 1.0f / 1024.0f;

    zero_init_k<<<1, 1024>>>();
    { dim3 g(3, 64); colmean_k<<<g, 256>>>(W_e); }
    { long nv = (long)B_DIM * S_DIM * E_DIM;
      embed_k<<<(int)((nv + 255) / 256), 256>>>(x, W_e); }
    { dim3 g(B_DIM, 16); bvec_k<<<g, E_DIM>>>(B_lr); }

    // fp16 + K-perm operand conversions
    convert_perm_k<<<4096, 256>>>(W_e,   p_WeH, (long)V_DIM * E_DIM);
    convert_perm_k<<<1024, 256>>>(W_p,   p_WpH, (long)Q_DIM * E_DIM);
    convert_perm_k<<<1024, 256>>>(ff_w1, p_w1H, (long)DFF_DIM * E_DIM);
    convert_perm_k<<<1024, 256>>>(ff_w2, p_w2H, (long)E_DIM * DFF_DIM);

    { dim3 g(24, 24, 12), b(32, 8);
      transpose_head_k<<<g, b>>>(W_q, p_WqT);
      transpose_head_k<<<g, b>>>(W_k, p_WkT);
      transpose_head_k<<<g, b>>>(W_v, p_WvT); }

    // Q[h] = W_p @ WqT[h]^T   (perm-out)
    { dim3 g(9, 6, H_DIM);
      gemm_h<false, false, true, __half><<<g, 512, GEMMH_SMEM>>>(p_WpH, p_WqT, p_Q,
          Q_DIM, E_DIM, E_DIM, E_DIM, E_DIM, E_DIM,
          0L, EE, (long)Q_DIM * E_DIM, 0L, 1, BIG, 0L,
          nullptr, 1, 1.0f, nullptr, 0L, 1.0f); }
    // K[h] = W_p[:1024] @ WkT[h]^T
    { dim3 g(8, 6, H_DIM);
      gemm_h<false, false, true, __half><<<g, 512, GEMMH_SMEM>>>(p_WpH, p_WkT, p_K,
          S_DIM, E_DIM, E_DIM, E_DIM, E_DIM, E_DIM,
          0L, EE, (long)S_DIM * E_DIM, 0L, 1, BIG, 0L,
          nullptr, 1, 1.0f, nullptr, 0L, 1.0f); }
    // attnT[q, h*S+s] = Q[h] @ K[h]^T
    { dim3 g(9, 8, H_DIM);
      gemm_h<false, false, true, __half><<<g, 512, GEMMH_SMEM>>>(p_Q, p_K, p_attnT,
          Q_DIM, S_DIM, E_DIM, E_DIM, E_DIM, HS_DIM,
          (long)Q_DIM * E_DIM, (long)S_DIM * E_DIM, (long)S_DIM, 0L, 1, BIG, 0L,
          nullptr, 1, 1.0f, nullptr, 0L, 1.0f); }
    softmax_h<<<Q_DIM * H_DIM, 256>>>(p_attnT);

    // VtT[b][e][h*S+s] = A_lr[h] * (WvT[h] @ v[b]^T); z = h*B + b
    { dim3 g(6, 8, H_DIM * B_DIM);
      gemm_h<false, false, true, __half><<<g, 512, GEMMH_SMEM>>>(p_WvT, p_v, p_VtT,
          E_DIM, S_DIM, E_DIM, E_DIM, E_DIM, HS_DIM,
          EE, (long)S_DIM * E_DIM, (long)S_DIM, (long)E_DIM * HS, B_DIM, B_DIM, 0L,
          A_lr, H_DIM, 1.0f, nullptr, 0L, 1.0f); }
    // f[b] = (attnT @ VtT[b]^T)/S + bvec[b]; stored x1024
    { dim3 g(9, 6, B_DIM);
      gemm_h<false, false, true, __half><<<g, 512, GEMMH_SMEM>>>(p_attnT, p_VtT, p_f,
          Q_DIM, E_DIM, HS_DIM, HS_DIM, HS_DIM, E_DIM,
          0L, (long)E_DIM * HS, (long)Q_DIM * E_DIM, 0L, 1, BIG, 0L,
          nullptr, 1, 1.0f / (float)S_DIM, p_bvec, (long)E_DIM, SS); }
    // h1 = gelu(f @ ff_w1^T); input x1024 undone by alpha; stored x1024
    { dim3 g(33, 24, 1);
      gemm_h<true, false, true, __half><<<g, 512, GEMMH_SMEM>>>(p_f, p_w1H, p_h1,
          B_DIM * Q_DIM, DFF_DIM, E_DIM, E_DIM, E_DIM, DFF_DIM,
          0L, 0L, 0L, 0L, 1, BIG, 0L,
          nullptr, 1, ISS, nullptr, 0L, SS); }
    // f2 = h1 @ ff_w2^T; stored x1024
    { dim3 g(33, 6, 1);
      gemm_h<false, false, true, __half><<<g, 512, GEMMH_SMEM>>>(p_h1, p_w2H, p_f2,
          B_DIM * Q_DIM, E_DIM, DFF_DIM, DFF_DIM, DFF_DIM, E_DIM,
          0L, 0L, 0L, 0L, 1, BIG, 0L,
          nullptr, 1, ISS, nullptr, 0L, SS); }
    // logits: M=4096 (batch folded), N=50257; natural output, alpha undoes x1024
    { dim3 g(32, 393, 1);
      gemm_h<false, true, false, float><<<g, 512, GEMMH_SMEM>>>(p_f2, p_WeH, out,
          B_DIM * S_DIM, V_DIM, E_DIM, E_DIM, E_DIM, V_DIM,
          0L, 0L, 0L, 0L, 1, BIG, (long)Q_DIM * E_DIM,
          nullptr, 1, ISS, nullptr, 0L, 1.0f); }
}